// round 1
// baseline (speedup 1.0000x reference)
#include <cuda_runtime.h>
#include <math.h>

#define NN 50000
#define EE 800000
#define HD 96
#define FIN 32
#define EDIM 16
#define LL 3
#define BB 50

// Scratch (device globals: no allocation allowed)
__device__ float g_h[NN * HD];     // node hidden state
__device__ float g_Pb[NN * HD];    // h @ W1a + b1   (edge MLP src part)
__device__ float g_Q[NN * HD];     // h @ W1b        (edge MLP dst part)
__device__ float g_agg[NN * HD];   // aggregated messages
__device__ float g_d2[EE];         // squared edge distances
__device__ float g_pool[BB * HD];  // per-graph sums
__device__ float g_cnt[BB];        // per-graph counts

__device__ __forceinline__ float silu_f(float x) {
    return x / (1.0f + __expf(-x));
}

__device__ __forceinline__ void red_add4(float* p, float4 v) {
    asm volatile("red.global.add.v4.f32 [%0], {%1,%2,%3,%4};"
                 :: "l"(p), "f"(v.x), "f"(v.y), "f"(v.z), "f"(v.w)
                 : "memory");
}

// ---------------------------------------------------------------------------
// encoder: h = x @ We + be
// ---------------------------------------------------------------------------
__global__ void __launch_bounds__(96) k_encoder(const float* __restrict__ x,
                                                const float* __restrict__ We,
                                                const float* __restrict__ be) {
    __shared__ float sW[FIN * HD];
    __shared__ float sb[HD];
    __shared__ float xrow[FIN];
    const int j = threadIdx.x;
    for (int i = j; i < FIN * HD; i += 96) sW[i] = We[i];
    sb[j] = be[j];
    __syncthreads();
    for (int i = blockIdx.x; i < NN; i += gridDim.x) {
        if (j < FIN) xrow[j] = x[i * FIN + j];
        __syncthreads();
        float t = sb[j];
#pragma unroll
        for (int k = 0; k < FIN; k++) t = fmaf(xrow[k], sW[k * HD + j], t);
        g_h[i * HD + j] = t;
        __syncthreads();
    }
}

// ---------------------------------------------------------------------------
// d2 = ||pos[src]-pos[dst]||^2 per edge
// ---------------------------------------------------------------------------
__global__ void k_d2(const float* __restrict__ pos, const int* __restrict__ ei) {
    for (int e = blockIdx.x * blockDim.x + threadIdx.x; e < EE;
         e += gridDim.x * blockDim.x) {
        const int s = ei[e], d = ei[EE + e];
        const float dx = pos[s * 3 + 0] - pos[d * 3 + 0];
        const float dy = pos[s * 3 + 1] - pos[d * 3 + 1];
        const float dz = pos[s * 3 + 2] - pos[d * 3 + 2];
        g_d2[e] = dx * dx + dy * dy + dz * dz;
    }
}

__global__ void k_zero_agg() {
    for (int i = blockIdx.x * blockDim.x + threadIdx.x; i < NN * HD;
         i += gridDim.x * blockDim.x)
        g_agg[i] = 0.0f;
}

__global__ void k_zero_pool() {
    const int i = blockIdx.x * blockDim.x + threadIdx.x;
    if (i < BB * HD) g_pool[i] = 0.0f;
    if (i < BB) g_cnt[i] = 0.0f;
}

// ---------------------------------------------------------------------------
// node_pre: Pb = h @ W1a + b1 ; Q = h @ W1b   (W1a = eW1 rows 0..95, W1b rows 96..191)
// dynamic smem: [sWa 9216][sWb 9216][sb1 96][hrow 96]
// ---------------------------------------------------------------------------
__global__ void __launch_bounds__(96) k_node_pre(const float* __restrict__ eW1l,
                                                 const float* __restrict__ eb1l) {
    extern __shared__ float dsm[];
    float* sWa = dsm;
    float* sWb = dsm + HD * HD;
    float* sb1 = sWb + HD * HD;
    float* hrow = sb1 + HD;
    const int j = threadIdx.x;
    for (int i = j; i < HD * HD; i += 96) {
        sWa[i] = eW1l[i];
        sWb[i] = eW1l[HD * HD + i];
    }
    sb1[j] = eb1l[j];
    __syncthreads();
    for (int i = blockIdx.x; i < NN; i += gridDim.x) {
        hrow[j] = g_h[i * HD + j];
        __syncthreads();
        float p = sb1[j], q = 0.0f;
#pragma unroll 8
        for (int k = 0; k < HD; k++) {
            const float hk = hrow[k];
            p = fmaf(hk, sWa[k * HD + j], p);
            q = fmaf(hk, sWb[k * HD + j], q);
        }
        g_Pb[i * HD + j] = p;
        g_Q[i * HD + j] = q;
        __syncthreads();
    }
}

// ---------------------------------------------------------------------------
// edge kernel: per edge e
//   t = Pb[src] + Q[dst] + d2*wd + edge_attr @ W1c   (b1 folded into Pb)
//   u = silu(t); m = silu(u @ eW2 + b2); agg[dst] += m  (atomic)
// 96 threads, 128 edges/block in groups of 4.
// ---------------------------------------------------------------------------
__global__ void __launch_bounds__(96) k_edge(const int* __restrict__ ei,
                                             const float* __restrict__ edge_attr,
                                             const float* __restrict__ eW1l,
                                             const float* __restrict__ eW2l,
                                             const float* __restrict__ eb2l) {
    __shared__ __align__(16) float s_W2[HD * HD];
    __shared__ float s_W1c[EDIM * HD];
    __shared__ float s_wd[HD];
    __shared__ __align__(16) float s_b2[HD];
    __shared__ __align__(16) float u_sh[HD * 4];
    __shared__ float s_ea[4 * EDIM];
    __shared__ int s_src[4], s_dst[4];
    __shared__ float s_d2[4];

    const int j = threadIdx.x;
    for (int i = j; i < HD * HD; i += 96) s_W2[i] = eW2l[i];
    for (int i = j; i < EDIM * HD; i += 96) s_W1c[i] = eW1l[193 * HD + i];
    s_wd[j] = eW1l[192 * HD + j];
    s_b2[j] = eb2l[j];
    __syncthreads();

    const int e_base = blockIdx.x * 128;
    for (int g = 0; g < 32; ++g) {
        const int e0 = e_base + g * 4;
        if (j < 4) {
            s_src[j] = ei[e0 + j];
            s_dst[j] = ei[EE + e0 + j];
            s_d2[j] = g_d2[e0 + j];
        }
        if (j < 4 * EDIM) s_ea[j] = edge_attr[e0 * EDIM + j];
        __syncthreads();

        // Phase A: thread j computes u[j] for 4 edges
        float u[4];
#pragma unroll
        for (int e = 0; e < 4; e++) {
            const int si = s_src[e], di = s_dst[e];
            float t = g_Pb[si * HD + j] + g_Q[di * HD + j];
            t = fmaf(s_wd[j], s_d2[e], t);
#pragma unroll
            for (int k = 0; k < EDIM; k++)
                t = fmaf(s_ea[e * EDIM + k], s_W1c[k * HD + j], t);
            u[e] = silu_f(t);
        }
        *reinterpret_cast<float4*>(&u_sh[j * 4]) =
            make_float4(u[0], u[1], u[2], u[3]);
        __syncthreads();

        // Phase B: thread (e = j&3, c = j>>2) computes 4 cols of m for edge e
        const int e = j & 3, c = j >> 2;
        float4 acc = make_float4(0.f, 0.f, 0.f, 0.f);
#pragma unroll 12
        for (int k = 0; k < HD; k++) {
            const float uk = u_sh[k * 4 + e];
            const float4 w =
                *reinterpret_cast<const float4*>(&s_W2[k * HD + (c << 2)]);
            acc.x = fmaf(uk, w.x, acc.x);
            acc.y = fmaf(uk, w.y, acc.y);
            acc.z = fmaf(uk, w.z, acc.z);
            acc.w = fmaf(uk, w.w, acc.w);
        }
        const float4 b2 = *reinterpret_cast<const float4*>(&s_b2[c << 2]);
        float4 m;
        m.x = silu_f(acc.x + b2.x);
        m.y = silu_f(acc.y + b2.y);
        m.z = silu_f(acc.z + b2.z);
        m.w = silu_f(acc.w + b2.w);
        red_add4(&g_agg[s_dst[e] * HD + (c << 2)], m);
        __syncthreads();
    }
}

// ---------------------------------------------------------------------------
// node update: h += silu(h@nW1a + agg@nW1b + nb1) @ nW2 + nb2
// dynamic smem: [sA 9216][sB 9216][sC 9216][nb1 96][nb2 96][hrow 96][arow 96][urow 96]
// ---------------------------------------------------------------------------
__global__ void __launch_bounds__(96) k_node_update(const float* __restrict__ nW1l,
                                                    const float* __restrict__ nb1l,
                                                    const float* __restrict__ nW2l,
                                                    const float* __restrict__ nb2l) {
    extern __shared__ float dsm[];
    float* sA = dsm;
    float* sB = sA + HD * HD;
    float* sC = sB + HD * HD;
    float* snb1 = sC + HD * HD;
    float* snb2 = snb1 + HD;
    float* hrow = snb2 + HD;
    float* arow = hrow + HD;
    float* urow = arow + HD;
    const int j = threadIdx.x;
    for (int i = j; i < HD * HD; i += 96) {
        sA[i] = nW1l[i];
        sB[i] = nW1l[HD * HD + i];
        sC[i] = nW2l[i];
    }
    snb1[j] = nb1l[j];
    snb2[j] = nb2l[j];
    __syncthreads();
    for (int i = blockIdx.x; i < NN; i += gridDim.x) {
        hrow[j] = g_h[i * HD + j];
        arow[j] = g_agg[i * HD + j];
        __syncthreads();
        float t = snb1[j];
#pragma unroll 8
        for (int k = 0; k < HD; k++) {
            t = fmaf(hrow[k], sA[k * HD + j], t);
            t = fmaf(arow[k], sB[k * HD + j], t);
        }
        urow[j] = silu_f(t);
        __syncthreads();
        float o = snb2[j];
#pragma unroll 8
        for (int k = 0; k < HD; k++) o = fmaf(urow[k], sC[k * HD + j], o);
        g_h[i * HD + j] = hrow[j] + o;
        __syncthreads();
    }
}

// ---------------------------------------------------------------------------
// pooling
// ---------------------------------------------------------------------------
__global__ void __launch_bounds__(96) k_pool_acc(const int* __restrict__ batch) {
    const int j = threadIdx.x;
    for (int i = blockIdx.x; i < NN; i += gridDim.x) {
        const int b = batch[i];
        atomicAdd(&g_pool[b * HD + j], g_h[i * HD + j]);
        if (j == 0) atomicAdd(&g_cnt[b], 1.0f);
    }
}

__global__ void k_final(const float* __restrict__ Wl, const float* __restrict__ bl,
                        float* __restrict__ out) {
    const int b = threadIdx.x;
    if (b >= BB) return;
    float s = 0.0f;
#pragma unroll 8
    for (int jj = 0; jj < HD; jj++) s = fmaf(g_pool[b * HD + jj], Wl[jj], s);
    out[b] = s / fmaxf(g_cnt[b], 1.0f) + bl[0];
}

// ---------------------------------------------------------------------------
extern "C" void kernel_launch(void* const* d_in, const int* in_sizes, int n_in,
                              void* d_out, int out_size) {
    const float* x = (const float*)d_in[0];
    const float* pos = (const float*)d_in[1];
    const int* ei = (const int*)d_in[2];
    const float* edge_attr = (const float*)d_in[3];
    const int* batch = (const int*)d_in[4];
    const float* We = (const float*)d_in[5];
    const float* be = (const float*)d_in[6];
    const float* eW1 = (const float*)d_in[7];
    const float* eb1 = (const float*)d_in[8];
    const float* eW2 = (const float*)d_in[9];
    const float* eb2 = (const float*)d_in[10];
    const float* nW1 = (const float*)d_in[11];
    const float* nb1 = (const float*)d_in[12];
    const float* nW2 = (const float*)d_in[13];
    const float* nb2 = (const float*)d_in[14];
    const float* Wl = (const float*)d_in[15];
    const float* bl = (const float*)d_in[16];
    float* out = (float*)d_out;

    const int smem_pre = (2 * HD * HD + 2 * HD) * 4;          // 74496 B
    const int smem_upd = (3 * HD * HD + 5 * HD) * 4;          // 112512 B
    cudaFuncSetAttribute(k_node_pre, cudaFuncAttributeMaxDynamicSharedMemorySize,
                         smem_pre);
    cudaFuncSetAttribute(k_node_update,
                         cudaFuncAttributeMaxDynamicSharedMemorySize, smem_upd);

    k_encoder<<<512, 96>>>(x, We, be);
    k_d2<<<3125, 256>>>(pos, ei);

    for (int l = 0; l < LL; ++l) {
        const float* eW1l = eW1 + l * 209 * HD;
        const float* eb1l = eb1 + l * HD;
        const float* eW2l = eW2 + l * HD * HD;
        const float* eb2l = eb2 + l * HD;
        const float* nW1l = nW1 + l * 2 * HD * HD;
        const float* nb1l = nb1 + l * HD;
        const float* nW2l = nW2 + l * HD * HD;
        const float* nb2l = nb2 + l * HD;

        k_zero_agg<<<2048, 256>>>();
        k_node_pre<<<888, 96, smem_pre>>>(eW1l, eb1l);
        k_edge<<<EE / 128, 96>>>(ei, edge_attr, eW1l, eW2l, eb2l);
        k_node_update<<<592, 96, smem_upd>>>(nW1l, nb1l, nW2l, nb2l);
    }

    k_zero_pool<<<20, 256>>>();
    k_pool_acc<<<1024, 96>>>(batch);
    k_final<<<1, 64>>>(Wl, bl, out);
}

// round 5
// speedup vs baseline: 2.0525x; 2.0525x over previous
#include <cuda_runtime.h>
#include <math.h>

#define NN 50000
#define EE 800000
#define HD 96
#define FIN 32
#define EDIM 16
#define LL 3
#define BB 50

// Scratch (device globals: no allocation allowed)
__device__ float g_h[NN * HD];
__device__ float g_Pb[NN * HD];
__device__ float g_Q[NN * HD];
__device__ float g_agg[NN * HD];
__device__ float g_d2[EE];
__device__ float g_pool[BB * HD];
__device__ float g_cnt[BB];

__device__ __forceinline__ float silu_f(float x) {
    return x / (1.0f + __expf(-x));
}

__device__ __forceinline__ void red_add4(float* p, float4 v) {
    asm volatile("red.global.add.v4.f32 [%0], {%1,%2,%3,%4};"
                 :: "l"(p), "f"(v.x), "f"(v.y), "f"(v.z), "f"(v.w)
                 : "memory");
}

__device__ __forceinline__ unsigned long long pack2(float x) {
    unsigned long long r;
    asm("mov.b64 %0, {%1, %1};" : "=l"(r) : "f"(x));
    return r;
}

__device__ __forceinline__ void fma2(unsigned long long& d,
                                     unsigned long long a,
                                     unsigned long long b) {
    asm("fma.rn.f32x2 %0, %1, %2, %0;" : "+l"(d) : "l"(a), "l"(b));
}

__device__ __forceinline__ void unpack2(unsigned long long v, float& lo, float& hi) {
    asm("mov.b64 {%0, %1}, %2;" : "=f"(lo), "=f"(hi) : "l"(v));
}

// ---------------------------------------------------------------------------
// encoder: h = x @ We + be
// ---------------------------------------------------------------------------
__global__ void __launch_bounds__(96) k_encoder(const float* __restrict__ x,
                                                const float* __restrict__ We,
                                                const float* __restrict__ be) {
    __shared__ float sW[FIN * HD];
    __shared__ float sb[HD];
    __shared__ float xrow[FIN];
    const int j = threadIdx.x;
    for (int i = j; i < FIN * HD; i += 96) sW[i] = We[i];
    sb[j] = be[j];
    __syncthreads();
    for (int i = blockIdx.x; i < NN; i += gridDim.x) {
        if (j < FIN) xrow[j] = x[i * FIN + j];
        __syncthreads();
        float t = sb[j];
#pragma unroll
        for (int k = 0; k < FIN; k++) t = fmaf(xrow[k], sW[k * HD + j], t);
        g_h[i * HD + j] = t;
        __syncthreads();
    }
}

__global__ void k_d2(const float* __restrict__ pos, const int* __restrict__ ei) {
    for (int e = blockIdx.x * blockDim.x + threadIdx.x; e < EE;
         e += gridDim.x * blockDim.x) {
        const int s = ei[e], d = ei[EE + e];
        const float dx = pos[s * 3 + 0] - pos[d * 3 + 0];
        const float dy = pos[s * 3 + 1] - pos[d * 3 + 1];
        const float dz = pos[s * 3 + 2] - pos[d * 3 + 2];
        g_d2[e] = dx * dx + dy * dy + dz * dz;
    }
}

__global__ void k_zero_agg() {
    for (int i = blockIdx.x * blockDim.x + threadIdx.x; i < NN * HD;
         i += gridDim.x * blockDim.x)
        g_agg[i] = 0.0f;
}

__global__ void k_zero_pool() {
    const int i = blockIdx.x * blockDim.x + threadIdx.x;
    if (i < BB * HD) g_pool[i] = 0.0f;
    if (i < BB) g_cnt[i] = 0.0f;
}

// ---------------------------------------------------------------------------
// node_pre: Pb = h @ W1a + b1 ; Q = h @ W1b
// 384 threads: j = t%96, rs = t/96; 16 rows/iter, 4 rows/thread.
// dyn smem: [sWa 9216][sWb 9216][sb1 96][hrows 1536]
// ---------------------------------------------------------------------------
__global__ void __launch_bounds__(384) k_node_pre(const float* __restrict__ eW1l,
                                                  const float* __restrict__ eb1l) {
    extern __shared__ float sm[];
    float* sWa = sm;
    float* sWb = sm + HD * HD;
    float* sb1 = sWb + HD * HD;
    float* hrows = sb1 + HD;
    const int t = threadIdx.x;
    const int j = t % 96;
    const int rs = t / 96;
    for (int i = t; i < HD * HD; i += 384) {
        sWa[i] = eW1l[i];
        sWb[i] = eW1l[HD * HD + i];
    }
    if (t < HD) sb1[t] = eb1l[t];
    __syncthreads();
    for (int base = blockIdx.x * 16; base < NN; base += gridDim.x * 16) {
        for (int i = t; i < 16 * HD; i += 384) hrows[i] = g_h[base * HD + i];
        __syncthreads();
        float ap[4], aq[4];
#pragma unroll
        for (int q = 0; q < 4; q++) { ap[q] = sb1[j]; aq[q] = 0.0f; }
#pragma unroll 8
        for (int k = 0; k < HD; k++) {
            const float wa = sWa[k * HD + j];
            const float wb = sWb[k * HD + j];
#pragma unroll
            for (int q = 0; q < 4; q++) {
                const float hk = hrows[(rs * 4 + q) * HD + k];
                ap[q] = fmaf(hk, wa, ap[q]);
                aq[q] = fmaf(hk, wb, aq[q]);
            }
        }
#pragma unroll
        for (int q = 0; q < 4; q++) {
            const int r = base + rs * 4 + q;
            g_Pb[r * HD + j] = ap[q];
            g_Q[r * HD + j] = aq[q];
        }
        __syncthreads();
    }
}

// ---------------------------------------------------------------------------
// fused edge kernel, 256 threads, 128 edges per block.
// Phase A: u = silu(Pb[src]+Q[dst]+wd*d2+ea@W1c)  (warp w -> edges 16w..16w+15)
// Phase B: m = silu(u @ W2 + b2) via f32x2, then red.add.v4 into agg[dst].
//   thread: edges {lane+32i}, cols {12w..12w+11}
// dyn smem floats: [W2 9216][u 128*97][ea 2048][b2 96][d2 128][src 128][dst 128]
// ---------------------------------------------------------------------------
#define EDGE_SMEM_F (HD * HD + 128 * 97 + 2048 + 96 + 128 + 128 + 128)
__global__ void __launch_bounds__(256, 2) k_edge(const int* __restrict__ ei,
                                                 const float* __restrict__ edge_attr,
                                                 const float* __restrict__ eW1l,
                                                 const float* __restrict__ eW2l,
                                                 const float* __restrict__ eb2l) {
    extern __shared__ float sm[];
    float* s_W2 = sm;                       // 9216
    float* u_sh = s_W2 + HD * HD;           // 128*97
    float* s_ea = u_sh + 128 * 97;          // 2048
    float* s_b2 = s_ea + 2048;              // 96
    float* s_d2 = s_b2 + 96;                // 128
    int* s_src = (int*)(s_d2 + 128);        // 128
    int* s_dst = s_src + 128;               // 128

    const int t = threadIdx.x;
    const int lane = t & 31;
    const int w = t >> 5;
    const int e_base = blockIdx.x * 128;

    for (int i = t; i < HD * HD; i += 256) s_W2[i] = eW2l[i];
    {
        const float4* eap = (const float4*)(edge_attr + (long long)e_base * EDIM);
        float4* sep = (float4*)s_ea;
        for (int i = t; i < 512; i += 256) sep[i] = eap[i];
    }
    if (t < HD) s_b2[t] = eb2l[t];
    if (t < 128) {
        s_src[t] = ei[e_base + t];
        s_dst[t] = ei[EE + e_base + t];
        s_d2[t] = g_d2[e_base + t];
    }

    // W1c (rows 193..208) and wd (row 192) in registers
    float rW1c[EDIM][3];
    float wd[3];
#pragma unroll
    for (int m = 0; m < 3; m++) {
        wd[m] = eW1l[192 * HD + lane + 32 * m];
#pragma unroll
        for (int k = 0; k < EDIM; k++)
            rW1c[k][m] = eW1l[(193 + k) * HD + lane + 32 * m];
    }
    __syncthreads();

    // ---- Phase A ----
    for (int el = 0; el < 16; el++) {
        const int e = w * 16 + el;
        const int si = s_src[e], di = s_dst[e];
        const float d2e = s_d2[e];
        float tv[3];
#pragma unroll
        for (int m = 0; m < 3; m++)
            tv[m] = g_Pb[si * HD + lane + 32 * m] + g_Q[di * HD + lane + 32 * m]
                    + wd[m] * d2e;
#pragma unroll
        for (int k = 0; k < EDIM; k++) {
            const float eak = s_ea[e * EDIM + k];
#pragma unroll
            for (int m = 0; m < 3; m++) tv[m] = fmaf(eak, rW1c[k][m], tv[m]);
        }
#pragma unroll
        for (int m = 0; m < 3; m++)
            u_sh[e * 97 + lane + 32 * m] = silu_f(tv[m]);
    }
    __syncthreads();

    // ---- Phase B (f32x2) ----
    unsigned long long acc[4][6];
#pragma unroll
    for (int i = 0; i < 4; i++)
#pragma unroll
        for (int m = 0; m < 6; m++) acc[i][m] = 0ull;

    const float* w2p = s_W2 + 12 * w;
#pragma unroll 4
    for (int k = 0; k < HD; k++) {
        unsigned long long wv[6];
#pragma unroll
        for (int m = 0; m < 6; m++)
            wv[m] = *reinterpret_cast<const unsigned long long*>(&w2p[k * HD + 2 * m]);
#pragma unroll
        for (int i = 0; i < 4; i++) {
            const unsigned long long up = pack2(u_sh[(lane + 32 * i) * 97 + k]);
#pragma unroll
            for (int m = 0; m < 6; m++) fma2(acc[i][m], up, wv[m]);
        }
    }

    float b2v[12];
#pragma unroll
    for (int c = 0; c < 12; c++) b2v[c] = s_b2[12 * w + c];

#pragma unroll
    for (int i = 0; i < 4; i++) {
        const int e = lane + 32 * i;
        const int di = s_dst[e];
        float mv[12];
#pragma unroll
        for (int m = 0; m < 6; m++) unpack2(acc[i][m], mv[2 * m], mv[2 * m + 1]);
#pragma unroll
        for (int c = 0; c < 12; c++) mv[c] = silu_f(mv[c] + b2v[c]);
        float* dstp = &g_agg[di * HD + 12 * w];
        red_add4(dstp + 0, make_float4(mv[0], mv[1], mv[2], mv[3]));
        red_add4(dstp + 4, make_float4(mv[4], mv[5], mv[6], mv[7]));
        red_add4(dstp + 8, make_float4(mv[8], mv[9], mv[10], mv[11]));
    }
}

// ---------------------------------------------------------------------------
// node update: h += silu(h@nW1a + agg@nW1b + nb1) @ nW2 + nb2
// 384 threads, 16 rows/iter, 4 rows/thread.
// dyn smem: [sA 9216][sB 9216][sC 9216][nb1 96][nb2 96][hrows 1536][arows 1536][urows 1536]
// ---------------------------------------------------------------------------
__global__ void __launch_bounds__(384) k_node_update(const float* __restrict__ nW1l,
                                                     const float* __restrict__ nb1l,
                                                     const float* __restrict__ nW2l,
                                                     const float* __restrict__ nb2l) {
    extern __shared__ float sm[];
    float* sA = sm;
    float* sB = sA + HD * HD;
    float* sC = sB + HD * HD;
    float* snb1 = sC + HD * HD;
    float* snb2 = snb1 + HD;
    float* hrows = snb2 + HD;
    float* arows = hrows + 16 * HD;
    float* urows = arows + 16 * HD;
    const int t = threadIdx.x;
    const int j = t % 96;
    const int rs = t / 96;
    for (int i = t; i < HD * HD; i += 384) {
        sA[i] = nW1l[i];
        sB[i] = nW1l[HD * HD + i];
        sC[i] = nW2l[i];
    }
    if (t < HD) { snb1[t] = nb1l[t]; snb2[t] = nb2l[t]; }
    __syncthreads();
    for (int base = blockIdx.x * 16; base < NN; base += gridDim.x * 16) {
        for (int i = t; i < 16 * HD; i += 384) {
            hrows[i] = g_h[base * HD + i];
            arows[i] = g_agg[base * HD + i];
        }
        __syncthreads();
        float u[4];
#pragma unroll
        for (int q = 0; q < 4; q++) u[q] = snb1[j];
#pragma unroll 8
        for (int k = 0; k < HD; k++) {
            const float wa = sA[k * HD + j];
            const float wb = sB[k * HD + j];
#pragma unroll
            for (int q = 0; q < 4; q++) {
                const int r = rs * 4 + q;
                u[q] = fmaf(hrows[r * HD + k], wa, u[q]);
                u[q] = fmaf(arows[r * HD + k], wb, u[q]);
            }
        }
#pragma unroll
        for (int q = 0; q < 4; q++)
            urows[(rs * 4 + q) * HD + j] = silu_f(u[q]);
        __syncthreads();
        float o[4];
#pragma unroll
        for (int q = 0; q < 4; q++) o[q] = snb2[j];
#pragma unroll 8
        for (int k = 0; k < HD; k++) {
            const float wc = sC[k * HD + j];
#pragma unroll
            for (int q = 0; q < 4; q++)
                o[q] = fmaf(urows[(rs * 4 + q) * HD + k], wc, o[q]);
        }
#pragma unroll
        for (int q = 0; q < 4; q++) {
            const int r = base + rs * 4 + q;
            g_h[r * HD + j] = hrows[(rs * 4 + q) * HD + j] + o[q];
        }
        __syncthreads();
    }
}

// ---------------------------------------------------------------------------
__global__ void __launch_bounds__(96) k_pool_acc(const int* __restrict__ batch) {
    const int j = threadIdx.x;
    for (int i = blockIdx.x; i < NN; i += gridDim.x) {
        const int b = batch[i];
        atomicAdd(&g_pool[b * HD + j], g_h[i * HD + j]);
        if (j == 0) atomicAdd(&g_cnt[b], 1.0f);
    }
}

__global__ void k_final(const float* __restrict__ Wl, const float* __restrict__ bl,
                        float* __restrict__ out) {
    const int b = threadIdx.x;
    if (b >= BB) return;
    float s = 0.0f;
#pragma unroll 8
    for (int jj = 0; jj < HD; jj++) s = fmaf(g_pool[b * HD + jj], Wl[jj], s);
    out[b] = s / fmaxf(g_cnt[b], 1.0f) + bl[0];
}

// ---------------------------------------------------------------------------
extern "C" void kernel_launch(void* const* d_in, const int* in_sizes, int n_in,
                              void* d_out, int out_size) {
    const float* x = (const float*)d_in[0];
    const float* pos = (const float*)d_in[1];
    const int* ei = (const int*)d_in[2];
    const float* edge_attr = (const float*)d_in[3];
    const int* batch = (const int*)d_in[4];
    const float* We = (const float*)d_in[5];
    const float* be = (const float*)d_in[6];
    const float* eW1 = (const float*)d_in[7];
    const float* eb1 = (const float*)d_in[8];
    const float* eW2 = (const float*)d_in[9];
    const float* eb2 = (const float*)d_in[10];
    const float* nW1 = (const float*)d_in[11];
    const float* nb1 = (const float*)d_in[12];
    const float* nW2 = (const float*)d_in[13];
    const float* nb2 = (const float*)d_in[14];
    const float* Wl = (const float*)d_in[15];
    const float* bl = (const float*)d_in[16];
    float* out = (float*)d_out;

    const int smem_pre = (2 * HD * HD + HD + 16 * HD) * 4;
    const int smem_edge = EDGE_SMEM_F * 4;
    const int smem_upd = (3 * HD * HD + 2 * HD + 3 * 16 * HD) * 4;
    cudaFuncSetAttribute(k_node_pre, cudaFuncAttributeMaxDynamicSharedMemorySize,
                         smem_pre);
    cudaFuncSetAttribute(k_edge, cudaFuncAttributeMaxDynamicSharedMemorySize,
                         smem_edge);
    cudaFuncSetAttribute(k_node_update,
                         cudaFuncAttributeMaxDynamicSharedMemorySize, smem_upd);

    k_encoder<<<888, 96>>>(x, We, be);
    k_d2<<<3125, 256>>>(pos, ei);

    for (int l = 0; l < LL; ++l) {
        const float* eW1l = eW1 + l * 209 * HD;
        const float* eb1l = eb1 + l * HD;
        const float* eW2l = eW2 + l * HD * HD;
        const float* eb2l = eb2 + l * HD;
        const float* nW1l = nW1 + l * 2 * HD * HD;
        const float* nb1l = nb1 + l * HD;
        const float* nW2l = nW2 + l * HD * HD;
        const float* nb2l = nb2 + l * HD;

        k_zero_agg<<<2048, 256>>>();
        k_node_pre<<<625, 384, smem_pre>>>(eW1l, eb1l);
        k_edge<<<EE / 128, 256, smem_edge>>>(ei, edge_attr, eW1l, eW2l, eb2l);
        k_node_update<<<625, 384, smem_upd>>>(nW1l, nb1l, nW2l, nb2l);
    }

    k_zero_pool<<<20, 256>>>();
    k_pool_acc<<<1024, 96>>>(batch);
    k_final<<<1, 64>>>(Wl, bl, out);
}

// round 11
// speedup vs baseline: 2.4407x; 1.1891x over previous
#include <cuda_runtime.h>
#include <cuda_bf16.h>
#include <math.h>
#include <stdint.h>

#define NN 50000
#define EE 800000
#define HD 96
#define FIN 32
#define EDIM 16
#define LL 3
#define BB 50

// Scratch (device globals: no allocation allowed)
__device__ float g_h[NN * HD];
__device__ float g_Pb[NN * HD];
__device__ float g_Q[NN * HD];
__device__ float g_agg[NN * HD];
__device__ float g_d2[EE];
__device__ float g_pool[BB * HD];
__device__ float g_cnt[BB];

__device__ __forceinline__ float silu_f(float x) {
    return x / (1.0f + __expf(-x));
}

__device__ __forceinline__ void red_add4(float* p, float4 v) {
    asm volatile("red.global.add.v4.f32 [%0], {%1,%2,%3,%4};"
                 :: "l"(p), "f"(v.x), "f"(v.y), "f"(v.z), "f"(v.w)
                 : "memory");
}

// ---------------------------------------------------------------------------
// legacy tensor core helpers (sm_80+ : compile OK for plain sm_103 target)
// ---------------------------------------------------------------------------
__device__ __forceinline__ void ldsm_x4(uint32_t* r, uint32_t addr) {
    asm volatile("ldmatrix.sync.aligned.m8n8.x4.shared.b16 {%0,%1,%2,%3}, [%4];"
                 : "=r"(r[0]), "=r"(r[1]), "=r"(r[2]), "=r"(r[3]) : "r"(addr));
}
__device__ __forceinline__ void ldsm_x2t(uint32_t* r, uint32_t addr) {
    asm volatile("ldmatrix.sync.aligned.m8n8.x2.trans.shared.b16 {%0,%1}, [%2];"
                 : "=r"(r[0]), "=r"(r[1]) : "r"(addr));
}
__device__ __forceinline__ void mma16816(float* d, const uint32_t* a,
                                         const uint32_t* b) {
    asm volatile(
        "mma.sync.aligned.m16n8k16.row.col.f32.bf16.bf16.f32 "
        "{%0,%1,%2,%3}, {%4,%5,%6,%7}, {%8,%9}, {%0,%1,%2,%3};"
        : "+f"(d[0]), "+f"(d[1]), "+f"(d[2]), "+f"(d[3])
        : "r"(a[0]), "r"(a[1]), "r"(a[2]), "r"(a[3]), "r"(b[0]), "r"(b[1]));
}

// ---------------------------------------------------------------------------
// encoder: h = x @ We + be
// ---------------------------------------------------------------------------
__global__ void __launch_bounds__(96) k_encoder(const float* __restrict__ x,
                                                const float* __restrict__ We,
                                                const float* __restrict__ be) {
    __shared__ float sW[FIN * HD];
    __shared__ float sb[HD];
    __shared__ float xrow[FIN];
    const int j = threadIdx.x;
    for (int i = j; i < FIN * HD; i += 96) sW[i] = We[i];
    sb[j] = be[j];
    __syncthreads();
    for (int i = blockIdx.x; i < NN; i += gridDim.x) {
        if (j < FIN) xrow[j] = x[i * FIN + j];
        __syncthreads();
        float t = sb[j];
#pragma unroll
        for (int k = 0; k < FIN; k++) t = fmaf(xrow[k], sW[k * HD + j], t);
        g_h[i * HD + j] = t;
        __syncthreads();
    }
}

__global__ void k_d2(const float* __restrict__ pos, const int* __restrict__ ei) {
    for (int e = blockIdx.x * blockDim.x + threadIdx.x; e < EE;
         e += gridDim.x * blockDim.x) {
        const int s = ei[e], d = ei[EE + e];
        const float dx = pos[s * 3 + 0] - pos[d * 3 + 0];
        const float dy = pos[s * 3 + 1] - pos[d * 3 + 1];
        const float dz = pos[s * 3 + 2] - pos[d * 3 + 2];
        g_d2[e] = dx * dx + dy * dy + dz * dz;
    }
}

__global__ void k_zero_agg() {
    for (int i = blockIdx.x * blockDim.x + threadIdx.x; i < NN * HD;
         i += gridDim.x * blockDim.x)
        g_agg[i] = 0.0f;
}

__global__ void k_zero_pool() {
    const int i = blockIdx.x * blockDim.x + threadIdx.x;
    if (i < BB * HD) g_pool[i] = 0.0f;
    if (i < BB) g_cnt[i] = 0.0f;
}

// ---------------------------------------------------------------------------
// node_pre: Pb = h @ W1a + b1 ; Q = h @ W1b
// ---------------------------------------------------------------------------
__global__ void __launch_bounds__(384) k_node_pre(const float* __restrict__ eW1l,
                                                  const float* __restrict__ eb1l) {
    extern __shared__ float sm[];
    float* sWa = sm;
    float* sWb = sm + HD * HD;
    float* sb1 = sWb + HD * HD;
    float* hrows = sb1 + HD;
    const int t = threadIdx.x;
    const int j = t % 96;
    const int rs = t / 96;
    for (int i = t; i < HD * HD; i += 384) {
        sWa[i] = eW1l[i];
        sWb[i] = eW1l[HD * HD + i];
    }
    if (t < HD) sb1[t] = eb1l[t];
    __syncthreads();
    for (int base = blockIdx.x * 16; base < NN; base += gridDim.x * 16) {
        for (int i = t; i < 16 * HD; i += 384) hrows[i] = g_h[base * HD + i];
        __syncthreads();
        float ap[4], aq[4];
#pragma unroll
        for (int q = 0; q < 4; q++) { ap[q] = sb1[j]; aq[q] = 0.0f; }
#pragma unroll 8
        for (int k = 0; k < HD; k++) {
            const float wa = sWa[k * HD + j];
            const float wb = sWb[k * HD + j];
#pragma unroll
            for (int q = 0; q < 4; q++) {
                const float hk = hrows[(rs * 4 + q) * HD + k];
                ap[q] = fmaf(hk, wa, ap[q]);
                aq[q] = fmaf(hk, wb, aq[q]);
            }
        }
#pragma unroll
        for (int q = 0; q < 4; q++) {
            const int r = base + rs * 4 + q;
            g_Pb[r * HD + j] = ap[q];
            g_Q[r * HD + j] = aq[q];
        }
        __syncthreads();
    }
}

// ---------------------------------------------------------------------------
// fused edge kernel with mma.sync bf16 (3-term hi/lo split), 256 thr, 128 edges.
// Phase A: u = silu(Pb[src]+Q[dst]+wd*d2+ea@W1c) -> bf16 hi/lo smem (208B rows)
// MMA: warp w owns edges 16w..16w+15 (one m16 stripe), D = u @ W2 fp32 in regs.
//   A frags preloaded (sync), then B = W2[k][n] via ldmatrix.x2.trans.
// D -> smem (aliases u region, safe post-sync), epilogue silu + red.add.v4.
// ---------------------------------------------------------------------------
#define OFF_UHI 0
#define OFF_ULO 26624
#define OFF_W2HI 53248
#define OFF_W2LO 73216
#define OFF_EA 93184
#define OFF_B2 101376
#define OFF_D2 101760
#define OFF_SRC 102272
#define OFF_DST 102784
#define SMEM_EDGE 103424

__global__ void __launch_bounds__(256, 2) k_edge(const int* __restrict__ ei,
                                                 const float* __restrict__ edge_attr,
                                                 const float* __restrict__ eW1l,
                                                 const float* __restrict__ eW2l,
                                                 const float* __restrict__ eb2l) {
    extern __shared__ char smc[];
    const int t = threadIdx.x;
    const int lane = t & 31;
    const int w = t >> 5;
    const int e_base = blockIdx.x * 128;
    const uint32_t sb = (uint32_t)__cvta_generic_to_shared(smc);

    // W2 -> bf16 hi/lo, layout [k][n], row stride 208 B
    for (int idx = t; idx < HD * HD; idx += 256) {
        const int k = idx / HD, n = idx % HD;
        const float v = eW2l[idx];
        const __nv_bfloat16 hb = __float2bfloat16(v);
        const __nv_bfloat16 lb = __float2bfloat16(v - __bfloat162float(hb));
        *reinterpret_cast<__nv_bfloat16*>(smc + OFF_W2HI + k * 208 + 2 * n) = hb;
        *reinterpret_cast<__nv_bfloat16*>(smc + OFF_W2LO + k * 208 + 2 * n) = lb;
    }
    {
        const float4* eap = (const float4*)(edge_attr + (size_t)e_base * EDIM);
        float4* sep = (float4*)(smc + OFF_EA);
        for (int i = t; i < 512; i += 256) sep[i] = eap[i];
    }
    float* s_b2 = (float*)(smc + OFF_B2);
    float* s_d2 = (float*)(smc + OFF_D2);
    int* s_src = (int*)(smc + OFF_SRC);
    int* s_dst = (int*)(smc + OFF_DST);
    if (t < 128) {
        s_src[t] = ei[e_base + t];
        s_dst[t] = ei[EE + e_base + t];
        s_d2[t] = g_d2[e_base + t];
    }
    if (t < HD) s_b2[t] = eb2l[t];

    // W1c (rows 193..208) and wd (row 192) in registers; j = lane + 32m
    float wd[3], rW1c[EDIM][3];
#pragma unroll
    for (int m = 0; m < 3; m++) {
        const int jj = lane + 32 * m;
        wd[m] = eW1l[192 * HD + jj];
#pragma unroll
        for (int k = 0; k < EDIM; k++)
            rW1c[k][m] = eW1l[(193 + k) * HD + jj];
    }
    const float* ea_s = (const float*)(smc + OFF_EA);
    __syncthreads();

    // ---- Phase A: warp w -> edges 16w..16w+15; u split to bf16 hi/lo ----
    for (int el = 0; el < 16; el++) {
        const int e = w * 16 + el;
        const int si = s_src[e], di = s_dst[e];
        const float d2e = s_d2[e];
        float tv[3];
#pragma unroll
        for (int m = 0; m < 3; m++)
            tv[m] = g_Pb[si * HD + lane + 32 * m] + g_Q[di * HD + lane + 32 * m]
                    + wd[m] * d2e;
#pragma unroll
        for (int k = 0; k < EDIM; k++) {
            const float eak = ea_s[e * EDIM + k];
#pragma unroll
            for (int m = 0; m < 3; m++) tv[m] = fmaf(eak, rW1c[k][m], tv[m]);
        }
        const int urow = e * 208;
#pragma unroll
        for (int m = 0; m < 3; m++) {
            const float u = silu_f(tv[m]);
            const __nv_bfloat16 hb = __float2bfloat16(u);
            const __nv_bfloat16 lb = __float2bfloat16(u - __bfloat162float(hb));
            const int boff = urow + 2 * (lane + 32 * m);
            *reinterpret_cast<__nv_bfloat16*>(smc + OFF_UHI + boff) = hb;
            *reinterpret_cast<__nv_bfloat16*>(smc + OFF_ULO + boff) = lb;
        }
    }
    __syncthreads();

    // ---- A fragment preload (before D aliases the u region) ----
    uint32_t Ah[6][4], Al[6][4];
    {
        const uint32_t aoff =
            (uint32_t)(w * 16 + (lane & 15)) * 208u + (uint32_t)(lane >> 4) * 16u;
#pragma unroll
        for (int kt = 0; kt < 6; kt++) {
            ldsm_x4(Ah[kt], sb + OFF_UHI + aoff + kt * 32);
            ldsm_x4(Al[kt], sb + OFF_ULO + aoff + kt * 32);
        }
    }
    __syncthreads();

    // ---- MMA: D[12][4] += Ahi*Bhi + Ahi*Blo + Alo*Bhi ----
    float D[12][4];
#pragma unroll
    for (int nt = 0; nt < 12; nt++)
#pragma unroll
        for (int i = 0; i < 4; i++) D[nt][i] = 0.0f;

    const uint32_t brow = (uint32_t)(lane & 15) * 208u;
#pragma unroll
    for (int kt = 0; kt < 6; kt++) {
        const uint32_t bko = (uint32_t)kt * (16u * 208u) + brow;
#pragma unroll
        for (int nt = 0; nt < 12; nt++) {
            uint32_t Bh[2], Bl[2];
            ldsm_x2t(Bh, sb + OFF_W2HI + bko + nt * 16);
            ldsm_x2t(Bl, sb + OFF_W2LO + bko + nt * 16);
            mma16816(D[nt], Ah[kt], Bh);
            mma16816(D[nt], Ah[kt], Bl);
            mma16816(D[nt], Al[kt], Bh);
        }
    }

    // ---- D -> smem (row stride 100 floats, aliases u region) ----
    {
        float* Dsm = (float*)smc;
        const int g = lane >> 2, q = lane & 3;
        const int r0 = w * 16 + g;
#pragma unroll
        for (int nt = 0; nt < 12; nt++) {
            const int c = nt * 8 + 2 * q;
            *reinterpret_cast<float2*>(Dsm + r0 * 100 + c) =
                make_float2(D[nt][0], D[nt][1]);
            *reinterpret_cast<float2*>(Dsm + (r0 + 8) * 100 + c) =
                make_float2(D[nt][2], D[nt][3]);
        }
    }
    __syncthreads();

    // ---- epilogue: thread t -> edge t>>1, col-half (t&1)*48 ----
    {
        const float* Dsm = (const float*)smc;
        const int e = t >> 1, ch = t & 1;
        const int di = s_dst[e];
        const float* drow = Dsm + e * 100 + ch * 48;
        const float* b2p = s_b2 + ch * 48;
        float* aggp = &g_agg[(size_t)di * HD + ch * 48];
#pragma unroll
        for (int q = 0; q < 12; q++) {
            float4 v = *reinterpret_cast<const float4*>(drow + 4 * q);
            v.x = silu_f(v.x + b2p[4 * q + 0]);
            v.y = silu_f(v.y + b2p[4 * q + 1]);
            v.z = silu_f(v.z + b2p[4 * q + 2]);
            v.w = silu_f(v.w + b2p[4 * q + 3]);
            red_add4(aggp + 4 * q, v);
        }
    }
}

// ---------------------------------------------------------------------------
// node update: h += silu(h@nW1a + agg@nW1b + nb1) @ nW2 + nb2
// ---------------------------------------------------------------------------
__global__ void __launch_bounds__(384) k_node_update(const float* __restrict__ nW1l,
                                                     const float* __restrict__ nb1l,
                                                     const float* __restrict__ nW2l,
                                                     const float* __restrict__ nb2l) {
    extern __shared__ float sm[];
    float* sA = sm;
    float* sB = sA + HD * HD;
    float* sC = sB + HD * HD;
    float* snb1 = sC + HD * HD;
    float* snb2 = snb1 + HD;
    float* hrows = snb2 + HD;
    float* arows = hrows + 16 * HD;
    float* urows = arows + 16 * HD;
    const int t = threadIdx.x;
    const int j = t % 96;
    const int rs = t / 96;
    for (int i = t; i < HD * HD; i += 384) {
        sA[i] = nW1l[i];
        sB[i] = nW1l[HD * HD + i];
        sC[i] = nW2l[i];
    }
    if (t < HD) { snb1[t] = nb1l[t]; snb2[t] = nb2l[t]; }
    __syncthreads();
    for (int base = blockIdx.x * 16; base < NN; base += gridDim.x * 16) {
        for (int i = t; i < 16 * HD; i += 384) {
            hrows[i] = g_h[base * HD + i];
            arows[i] = g_agg[base * HD + i];
        }
        __syncthreads();
        float u[4];
#pragma unroll
        for (int q = 0; q < 4; q++) u[q] = snb1[j];
#pragma unroll 8
        for (int k = 0; k < HD; k++) {
            const float wa = sA[k * HD + j];
            const float wb = sB[k * HD + j];
#pragma unroll
            for (int q = 0; q < 4; q++) {
                const int r = rs * 4 + q;
                u[q] = fmaf(hrows[r * HD + k], wa, u[q]);
                u[q] = fmaf(arows[r * HD + k], wb, u[q]);
            }
        }
#pragma unroll
        for (int q = 0; q < 4; q++)
            urows[(rs * 4 + q) * HD + j] = silu_f(u[q]);
        __syncthreads();
        float o[4];
#pragma unroll
        for (int q = 0; q < 4; q++) o[q] = snb2[j];
#pragma unroll 8
        for (int k = 0; k < HD; k++) {
            const float wc = sC[k * HD + j];
#pragma unroll
            for (int q = 0; q < 4; q++)
                o[q] = fmaf(urows[(rs * 4 + q) * HD + k], wc, o[q]);
        }
#pragma unroll
        for (int q = 0; q < 4; q++) {
            const int r = base + rs * 4 + q;
            g_h[r * HD + j] = hrows[(rs * 4 + q) * HD + j] + o[q];
        }
        __syncthreads();
    }
}

// ---------------------------------------------------------------------------
__global__ void __launch_bounds__(96) k_pool_acc(const int* __restrict__ batch) {
    const int j = threadIdx.x;
    for (int i = blockIdx.x; i < NN; i += gridDim.x) {
        const int b = batch[i];
        atomicAdd(&g_pool[b * HD + j], g_h[i * HD + j]);
        if (j == 0) atomicAdd(&g_cnt[b], 1.0f);
    }
}

__global__ void k_final(const float* __restrict__ Wl, const float* __restrict__ bl,
                        float* __restrict__ out) {
    const int b = threadIdx.x;
    if (b >= BB) return;
    float s = 0.0f;
#pragma unroll 8
    for (int jj = 0; jj < HD; jj++) s = fmaf(g_pool[b * HD + jj], Wl[jj], s);
    out[b] = s / fmaxf(g_cnt[b], 1.0f) + bl[0];
}

// ---------------------------------------------------------------------------
extern "C" void kernel_launch(void* const* d_in, const int* in_sizes, int n_in,
                              void* d_out, int out_size) {
    const float* x = (const float*)d_in[0];
    const float* pos = (const float*)d_in[1];
    const int* ei = (const int*)d_in[2];
    const float* edge_attr = (const float*)d_in[3];
    const int* batch = (const int*)d_in[4];
    const float* We = (const float*)d_in[5];
    const float* be = (const float*)d_in[6];
    const float* eW1 = (const float*)d_in[7];
    const float* eb1 = (const float*)d_in[8];
    const float* eW2 = (const float*)d_in[9];
    const float* eb2 = (const float*)d_in[10];
    const float* nW1 = (const float*)d_in[11];
    const float* nb1 = (const float*)d_in[12];
    const float* nW2 = (const float*)d_in[13];
    const float* nb2 = (const float*)d_in[14];
    const float* Wl = (const float*)d_in[15];
    const float* bl = (const float*)d_in[16];
    float* out = (float*)d_out;

    const int smem_pre = (2 * HD * HD + HD + 16 * HD) * 4;
    const int smem_upd = (3 * HD * HD + 2 * HD + 3 * 16 * HD) * 4;
    cudaFuncSetAttribute(k_node_pre, cudaFuncAttributeMaxDynamicSharedMemorySize,
                         smem_pre);
    cudaFuncSetAttribute(k_edge, cudaFuncAttributeMaxDynamicSharedMemorySize,
                         SMEM_EDGE);
    cudaFuncSetAttribute(k_node_update,
                         cudaFuncAttributeMaxDynamicSharedMemorySize, smem_upd);

    k_encoder<<<888, 96>>>(x, We, be);
    k_d2<<<3125, 256>>>(pos, ei);

    for (int l = 0; l < LL; ++l) {
        const float* eW1l = eW1 + l * 209 * HD;
        const float* eb1l = eb1 + l * HD;
        const float* eW2l = eW2 + l * HD * HD;
        const float* eb2l = eb2 + l * HD;
        const float* nW1l = nW1 + l * 2 * HD * HD;
        const float* nb1l = nb1 + l * HD;
        const float* nW2l = nW2 + l * HD * HD;
        const float* nb2l = nb2 + l * HD;

        k_zero_agg<<<2048, 256>>>();
        k_node_pre<<<625, 384, smem_pre>>>(eW1l, eb1l);
        k_edge<<<EE / 128, 256, SMEM_EDGE>>>(ei, edge_attr, eW1l, eW2l, eb2l);
        k_node_update<<<625, 384, smem_upd>>>(nW1l, nb1l, nW2l, nb2l);
    }

    k_zero_pool<<<20, 256>>>();
    k_pool_acc<<<1024, 96>>>(batch);
    k_final<<<1, 64>>>(Wl, bl, out);
}

// round 12
// speedup vs baseline: 2.8094x; 1.1511x over previous
#include <cuda_runtime.h>
#include <cuda_bf16.h>
#include <math.h>
#include <stdint.h>

#define NN 50000
#define EE 800000
#define HD 96
#define FIN 32
#define EDIM 16
#define LL 3
#define BB 50

// Scratch (device globals: no allocation allowed)
__device__ float g_h[NN * HD];
__device__ float g_Pb[NN * HD];
__device__ float g_Q[NN * HD];
__device__ float g_agg[NN * HD];
__device__ float g_d2[EE];
__device__ float g_pool[BB * HD];
__device__ float g_cnt[BB];

__device__ __forceinline__ float silu_f(float x) {
    return x / (1.0f + __expf(-x));
}

__device__ __forceinline__ void red_add4(float* p, float4 v) {
    asm volatile("red.global.add.v4.f32 [%0], {%1,%2,%3,%4};"
                 :: "l"(p), "f"(v.x), "f"(v.y), "f"(v.z), "f"(v.w)
                 : "memory");
}

// ---------------------------------------------------------------------------
// legacy tensor core helpers (sm_80+ : compile OK for plain sm_103 target)
// ---------------------------------------------------------------------------
__device__ __forceinline__ void ldsm_x4(uint32_t* r, uint32_t addr) {
    asm volatile("ldmatrix.sync.aligned.m8n8.x4.shared.b16 {%0,%1,%2,%3}, [%4];"
                 : "=r"(r[0]), "=r"(r[1]), "=r"(r[2]), "=r"(r[3]) : "r"(addr));
}
__device__ __forceinline__ void ldsm_x4t(uint32_t* r, uint32_t addr) {
    asm volatile("ldmatrix.sync.aligned.m8n8.x4.trans.shared.b16 {%0,%1,%2,%3}, [%4];"
                 : "=r"(r[0]), "=r"(r[1]), "=r"(r[2]), "=r"(r[3]) : "r"(addr));
}
__device__ __forceinline__ void mma16816(float* d, const uint32_t* a,
                                         const uint32_t* b) {
    asm volatile(
        "mma.sync.aligned.m16n8k16.row.col.f32.bf16.bf16.f32 "
        "{%0,%1,%2,%3}, {%4,%5,%6,%7}, {%8,%9}, {%0,%1,%2,%3};"
        : "+f"(d[0]), "+f"(d[1]), "+f"(d[2]), "+f"(d[3])
        : "r"(a[0]), "r"(a[1]), "r"(a[2]), "r"(a[3]), "r"(b[0]), "r"(b[1]));
}

__device__ __forceinline__ void split_bf16(float v, __nv_bfloat16& hb,
                                           __nv_bfloat16& lb) {
    hb = __float2bfloat16(v);
    lb = __float2bfloat16(v - __bfloat162float(hb));
}

// ---------------------------------------------------------------------------
// encoder: h = x @ We + be
// ---------------------------------------------------------------------------
__global__ void __launch_bounds__(96) k_encoder(const float* __restrict__ x,
                                                const float* __restrict__ We,
                                                const float* __restrict__ be) {
    __shared__ float sW[FIN * HD];
    __shared__ float sb[HD];
    __shared__ float xrow[FIN];
    const int j = threadIdx.x;
    for (int i = j; i < FIN * HD; i += 96) sW[i] = We[i];
    sb[j] = be[j];
    __syncthreads();
    for (int i = blockIdx.x; i < NN; i += gridDim.x) {
        if (j < FIN) xrow[j] = x[i * FIN + j];
        __syncthreads();
        float t = sb[j];
#pragma unroll
        for (int k = 0; k < FIN; k++) t = fmaf(xrow[k], sW[k * HD + j], t);
        g_h[i * HD + j] = t;
        __syncthreads();
    }
}

__global__ void k_d2(const float* __restrict__ pos, const int* __restrict__ ei) {
    for (int e = blockIdx.x * blockDim.x + threadIdx.x; e < EE;
         e += gridDim.x * blockDim.x) {
        const int s = ei[e], d = ei[EE + e];
        const float dx = pos[s * 3 + 0] - pos[d * 3 + 0];
        const float dy = pos[s * 3 + 1] - pos[d * 3 + 1];
        const float dz = pos[s * 3 + 2] - pos[d * 3 + 2];
        g_d2[e] = dx * dx + dy * dy + dz * dz;
    }
}

__global__ void k_zero_pool() {
    const int i = blockIdx.x * blockDim.x + threadIdx.x;
    if (i < BB * HD) g_pool[i] = 0.0f;
    if (i < BB) g_cnt[i] = 0.0f;
}

// ---------------------------------------------------------------------------
// node_pre (mma): [Pb|Q] = h @ [W1a|W1b] (+b1 on Pb). Also zeroes g_agg.
// 512 threads, persistent over 391 tiles of 128 rows.
// warp w: stripe w&7 (16 rows), n-half w>>3 (np 0..5 or 6..11 of 12 n-pairs).
// smem: Bhi[96][400B] Blo | Ahi[128][208B] Alo | b1
// ---------------------------------------------------------------------------
#define NP_BHI 0
#define NP_BLO 38400
#define NP_AHI 76800
#define NP_ALO 103424
#define NP_B1  130048
#define NP_SMEM 130432
#define NT_NP 391

__global__ void __launch_bounds__(512) k_node_pre(const float* __restrict__ eW1l,
                                                  const float* __restrict__ eb1l) {
    extern __shared__ char smc[];
    const uint32_t sbx = (uint32_t)__cvta_generic_to_shared(smc);
    const int t = threadIdx.x;
    const int lane = t & 31;
    const int w = t >> 5;
    const int stripe = w & 7;
    const int half = w >> 3;

    // B conversion: B[k][n2], n2<96 from W1a rows 0..95, n2>=96 from W1b rows 96..191
    for (int idx = t; idx < 96 * 192; idx += 512) {
        const int k = idx / 192;
        const int n2 = idx - k * 192;
        const int srow = k + ((n2 >= 96) ? 96 : 0);
        const int scol = (n2 >= 96) ? (n2 - 96) : n2;
        __nv_bfloat16 hb, lb;
        split_bf16(eW1l[srow * 96 + scol], hb, lb);
        const int off = k * 400 + 2 * n2;
        *reinterpret_cast<__nv_bfloat16*>(smc + NP_BHI + off) = hb;
        *reinterpret_cast<__nv_bfloat16*>(smc + NP_BLO + off) = lb;
    }
    if (t < 96) ((float*)(smc + NP_B1))[t] = eb1l[t];
    __syncthreads();
    const float* b1s = (const float*)(smc + NP_B1);

    for (int tile = blockIdx.x; tile < NT_NP; tile += gridDim.x) {
        const int base = tile * 128;
        // convert h tile -> A hi/lo
        for (int idx = t; idx < 128 * 96; idx += 512) {
            const int r = idx / 96;
            const int c = idx - r * 96;
            const int gi = base + r;
            const float v = (gi < NN) ? g_h[gi * 96 + c] : 0.0f;
            __nv_bfloat16 hb, lb;
            split_bf16(v, hb, lb);
            const int off = r * 208 + 2 * c;
            *reinterpret_cast<__nv_bfloat16*>(smc + NP_AHI + off) = hb;
            *reinterpret_cast<__nv_bfloat16*>(smc + NP_ALO + off) = lb;
        }
        // zero g_agg for this tile (float4)
        {
            const float4 z4 = make_float4(0.f, 0.f, 0.f, 0.f);
            for (int idx = t; idx < 128 * 24; idx += 512) {
                const int r = idx / 24;
                const int gi = base + r;
                if (gi < NN)
                    reinterpret_cast<float4*>(g_agg)[gi * 24 + (idx - r * 24)] = z4;
            }
        }
        __syncthreads();

        // A fragment preload
        uint32_t Ah[6][4], Al[6][4];
        {
            const uint32_t aoff = (uint32_t)(stripe * 16 + (lane & 15)) * 208u
                                  + (uint32_t)((lane >> 4) << 4);
#pragma unroll
            for (int kt = 0; kt < 6; kt++) {
                ldsm_x4(Ah[kt], sbx + NP_AHI + aoff + kt * 32);
                ldsm_x4(Al[kt], sbx + NP_ALO + aoff + kt * 32);
            }
        }

#pragma unroll
        for (int npl = 0; npl < 6; npl++) {
            const int np = half * 6 + npl;
            float D0[4] = {0.f, 0.f, 0.f, 0.f};
            float D1[4] = {0.f, 0.f, 0.f, 0.f};
#pragma unroll
            for (int kt = 0; kt < 6; kt++) {
                uint32_t Bh[4], Bl[4];
                const uint32_t bko = (uint32_t)(kt * 16 + (lane & 15)) * 400u
                                     + (uint32_t)(np * 32) + ((lane >> 4) << 4);
                ldsm_x4t(Bh, sbx + NP_BHI + bko);
                ldsm_x4t(Bl, sbx + NP_BLO + bko);
                mma16816(D0, Ah[kt], Bh);
                mma16816(D0, Ah[kt], Bl);
                mma16816(D0, Al[kt], Bh);
                mma16816(D1, Ah[kt], Bh + 2);
                mma16816(D1, Ah[kt], Bl + 2);
                mma16816(D1, Al[kt], Bh + 2);
            }
            const int rA = base + stripe * 16 + (lane >> 2);
            const int rB = rA + 8;
            const int q2 = 2 * (lane & 3);
            if (np < 6) {
                const int c0 = (2 * np) * 8 + q2;
                const int c1 = c0 + 8;
                if (rA < NN) {
                    *(float2*)&g_Pb[rA * 96 + c0] =
                        make_float2(D0[0] + b1s[c0], D0[1] + b1s[c0 + 1]);
                    *(float2*)&g_Pb[rA * 96 + c1] =
                        make_float2(D1[0] + b1s[c1], D1[1] + b1s[c1 + 1]);
                }
                if (rB < NN) {
                    *(float2*)&g_Pb[rB * 96 + c0] =
                        make_float2(D0[2] + b1s[c0], D0[3] + b1s[c0 + 1]);
                    *(float2*)&g_Pb[rB * 96 + c1] =
                        make_float2(D1[2] + b1s[c1], D1[3] + b1s[c1 + 1]);
                }
            } else {
                const int c0 = (2 * np) * 8 + q2 - 96;
                const int c1 = c0 + 8;
                if (rA < NN) {
                    *(float2*)&g_Q[rA * 96 + c0] = make_float2(D0[0], D0[1]);
                    *(float2*)&g_Q[rA * 96 + c1] = make_float2(D1[0], D1[1]);
                }
                if (rB < NN) {
                    *(float2*)&g_Q[rB * 96 + c0] = make_float2(D0[2], D0[3]);
                    *(float2*)&g_Q[rB * 96 + c1] = make_float2(D1[2], D1[3]);
                }
            }
        }
        __syncthreads();
    }
}

// ---------------------------------------------------------------------------
// fused edge kernel (persistent, mma bf16 3-term), 256 thr, tiles of 128 edges.
// ---------------------------------------------------------------------------
#define OFF_UHI 0
#define OFF_ULO 26624
#define OFF_W2HI 53248
#define OFF_W2LO 73216
#define OFF_EA 93184
#define OFF_B2 101376
#define OFF_D2 101760
#define OFF_SRC 102272
#define OFF_DST 102784
#define SMEM_EDGE 103424
#define NT_EDGE (EE / 128)

__global__ void __launch_bounds__(256, 2) k_edge(const int* __restrict__ ei,
                                                 const float* __restrict__ edge_attr,
                                                 const float* __restrict__ eW1l,
                                                 const float* __restrict__ eW2l,
                                                 const float* __restrict__ eb2l) {
    extern __shared__ char smc[];
    const int t = threadIdx.x;
    const int lane = t & 31;
    const int w = t >> 5;
    const uint32_t sb = (uint32_t)__cvta_generic_to_shared(smc);

    // ---- one-time setup ----
    for (int idx = t; idx < HD * HD; idx += 256) {
        const int k = idx / HD, n = idx % HD;
        __nv_bfloat16 hb, lb;
        split_bf16(eW2l[idx], hb, lb);
        *reinterpret_cast<__nv_bfloat16*>(smc + OFF_W2HI + k * 208 + 2 * n) = hb;
        *reinterpret_cast<__nv_bfloat16*>(smc + OFF_W2LO + k * 208 + 2 * n) = lb;
    }
    float* s_b2 = (float*)(smc + OFF_B2);
    float* s_d2 = (float*)(smc + OFF_D2);
    int* s_src = (int*)(smc + OFF_SRC);
    int* s_dst = (int*)(smc + OFF_DST);
    if (t < HD) s_b2[t] = eb2l[t];

    float wd[3], rW1c[EDIM][3];
#pragma unroll
    for (int m = 0; m < 3; m++) {
        const int jj = lane + 32 * m;
        wd[m] = eW1l[192 * HD + jj];
#pragma unroll
        for (int k = 0; k < EDIM; k++)
            rW1c[k][m] = eW1l[(193 + k) * HD + jj];
    }
    const float* ea_s = (const float*)(smc + OFF_EA);
    __syncthreads();

    for (int tile = blockIdx.x; tile < NT_EDGE; tile += gridDim.x) {
        const int e_base = tile * 128;
        // ---- tile loads ----
        if (t < 128) {
            s_src[t] = ei[e_base + t];
            s_dst[t] = ei[EE + e_base + t];
            s_d2[t] = g_d2[e_base + t];
        }
        {
            const float4* eap = (const float4*)(edge_attr + (size_t)e_base * EDIM);
            float4* sep = (float4*)(smc + OFF_EA);
            for (int i = t; i < 512; i += 256) sep[i] = eap[i];
        }
        __syncthreads();

        // ---- Phase A: warp w -> edges 16w..16w+15 ----
        for (int el = 0; el < 16; el++) {
            const int e = w * 16 + el;
            const int si = s_src[e], di = s_dst[e];
            const float d2e = s_d2[e];
            float tv[3];
#pragma unroll
            for (int m = 0; m < 3; m++)
                tv[m] = g_Pb[si * HD + lane + 32 * m]
                        + g_Q[di * HD + lane + 32 * m] + wd[m] * d2e;
#pragma unroll
            for (int k = 0; k < EDIM; k++) {
                const float eak = ea_s[e * EDIM + k];
#pragma unroll
                for (int m = 0; m < 3; m++) tv[m] = fmaf(eak, rW1c[k][m], tv[m]);
            }
            const int urow = e * 208;
#pragma unroll
            for (int m = 0; m < 3; m++) {
                const float u = silu_f(tv[m]);
                __nv_bfloat16 hb, lb;
                split_bf16(u, hb, lb);
                const int boff = urow + 2 * (lane + 32 * m);
                *reinterpret_cast<__nv_bfloat16*>(smc + OFF_UHI + boff) = hb;
                *reinterpret_cast<__nv_bfloat16*>(smc + OFF_ULO + boff) = lb;
            }
        }
        __syncthreads();

        // ---- A fragment preload ----
        uint32_t Ah[6][4], Al[6][4];
        {
            const uint32_t aoff = (uint32_t)(w * 16 + (lane & 15)) * 208u
                                  + (uint32_t)((lane >> 4) << 4);
#pragma unroll
            for (int kt = 0; kt < 6; kt++) {
                ldsm_x4(Ah[kt], sb + OFF_UHI + aoff + kt * 32);
                ldsm_x4(Al[kt], sb + OFF_ULO + aoff + kt * 32);
            }
        }
        __syncthreads();

        // ---- MMA ----
        float D[12][4];
#pragma unroll
        for (int nt = 0; nt < 12; nt++)
#pragma unroll
            for (int i = 0; i < 4; i++) D[nt][i] = 0.0f;

#pragma unroll
        for (int kt = 0; kt < 6; kt++) {
            const uint32_t bko = (uint32_t)(kt * 16 + (lane & 15)) * 208u
                                 + ((lane >> 4) << 4);
#pragma unroll
            for (int np = 0; np < 6; np++) {
                uint32_t Bh[4], Bl[4];
                ldsm_x4t(Bh, sb + OFF_W2HI + bko + np * 32);
                ldsm_x4t(Bl, sb + OFF_W2LO + bko + np * 32);
                mma16816(D[2 * np], Ah[kt], Bh);
                mma16816(D[2 * np], Ah[kt], Bl);
                mma16816(D[2 * np], Al[kt], Bh);
                mma16816(D[2 * np + 1], Ah[kt], Bh + 2);
                mma16816(D[2 * np + 1], Ah[kt], Bl + 2);
                mma16816(D[2 * np + 1], Al[kt], Bh + 2);
            }
        }

        // ---- D -> smem (row stride 100 floats, aliases u region) ----
        {
            float* Dsm = (float*)smc;
            const int g = lane >> 2, q = lane & 3;
            const int r0 = w * 16 + g;
#pragma unroll
            for (int nt = 0; nt < 12; nt++) {
                const int c = nt * 8 + 2 * q;
                *reinterpret_cast<float2*>(Dsm + r0 * 100 + c) =
                    make_float2(D[nt][0], D[nt][1]);
                *reinterpret_cast<float2*>(Dsm + (r0 + 8) * 100 + c) =
                    make_float2(D[nt][2], D[nt][3]);
            }
        }
        __syncthreads();

        // ---- epilogue ----
        {
            const float* Dsm = (const float*)smc;
            const int e = t >> 1, ch = t & 1;
            const int di = s_dst[e];
            const float* drow = Dsm + e * 100 + ch * 48;
            const float* b2p = s_b2 + ch * 48;
            float* aggp = &g_agg[(size_t)di * HD + ch * 48];
#pragma unroll
            for (int q = 0; q < 12; q++) {
                float4 v = *reinterpret_cast<const float4*>(drow + 4 * q);
                v.x = silu_f(v.x + b2p[4 * q + 0]);
                v.y = silu_f(v.y + b2p[4 * q + 1]);
                v.z = silu_f(v.z + b2p[4 * q + 2]);
                v.w = silu_f(v.w + b2p[4 * q + 3]);
                red_add4(aggp + 4 * q, v);
            }
        }
        __syncthreads();
    }
}

// ---------------------------------------------------------------------------
// node update (mma): h += silu([h|agg] @ nW1 + nb1) @ nW2 + nb2
// 256 threads, persistent over 782 tiles of 64 rows.
// warp w: stripe w&3 (16 rows), n-half w>>2 (np 0..2 or 3..5 of 6 n-pairs).
// ---------------------------------------------------------------------------
#define NU_B1HI 0
#define NU_B1LO 39936
#define NU_B2HI 79872
#define NU_B2LO 99840
#define NU_AHHI 119808
#define NU_AHLO 133120
#define NU_AAHI 146432
#define NU_AALO 159744
#define NU_UHI  173056
#define NU_ULO  186368
#define NU_NB1  199680
#define NU_NB2  200064
#define NU_SMEM 200448
#define NT_NU 782

__global__ void __launch_bounds__(256) k_node_update(const float* __restrict__ nW1l,
                                                     const float* __restrict__ nb1l,
                                                     const float* __restrict__ nW2l,
                                                     const float* __restrict__ nb2l) {
    extern __shared__ char smc[];
    const uint32_t sbx = (uint32_t)__cvta_generic_to_shared(smc);
    const int t = threadIdx.x;
    const int lane = t & 31;
    const int w = t >> 5;
    const int stripe = w & 3;
    const int nh = w >> 2;  // 0 or 1

    // B1 = nW1 [192][96] -> hi/lo stride 208
    for (int idx = t; idx < 192 * 96; idx += 256) {
        const int k = idx / 96, n = idx - (idx / 96) * 96;
        __nv_bfloat16 hb, lb;
        split_bf16(nW1l[idx], hb, lb);
        *reinterpret_cast<__nv_bfloat16*>(smc + NU_B1HI + k * 208 + 2 * n) = hb;
        *reinterpret_cast<__nv_bfloat16*>(smc + NU_B1LO + k * 208 + 2 * n) = lb;
    }
    // B2 = nW2 [96][96]
    for (int idx = t; idx < 96 * 96; idx += 256) {
        const int k = idx / 96, n = idx - (idx / 96) * 96;
        __nv_bfloat16 hb, lb;
        split_bf16(nW2l[idx], hb, lb);
        *reinterpret_cast<__nv_bfloat16*>(smc + NU_B2HI + k * 208 + 2 * n) = hb;
        *reinterpret_cast<__nv_bfloat16*>(smc + NU_B2LO + k * 208 + 2 * n) = lb;
    }
    if (t < 96) {
        ((float*)(smc + NU_NB1))[t] = nb1l[t];
        ((float*)(smc + NU_NB2))[t] = nb2l[t];
    }
    __syncthreads();
    const float* b1s = (const float*)(smc + NU_NB1);
    const float* b2s = (const float*)(smc + NU_NB2);

    for (int tile = blockIdx.x; tile < NT_NU; tile += gridDim.x) {
        const int base = tile * 64;
        // convert h and agg tiles
        for (int idx = t; idx < 64 * 96; idx += 256) {
            const int r = idx / 96;
            const int c = idx - r * 96;
            const int gi = base + r;
            const int off = r * 208 + 2 * c;
            float vh = 0.f, va = 0.f;
            if (gi < NN) {
                vh = g_h[gi * 96 + c];
                va = g_agg[gi * 96 + c];
            }
            __nv_bfloat16 hb, lb;
            split_bf16(vh, hb, lb);
            *reinterpret_cast<__nv_bfloat16*>(smc + NU_AHHI + off) = hb;
            *reinterpret_cast<__nv_bfloat16*>(smc + NU_AHLO + off) = lb;
            split_bf16(va, hb, lb);
            *reinterpret_cast<__nv_bfloat16*>(smc + NU_AAHI + off) = hb;
            *reinterpret_cast<__nv_bfloat16*>(smc + NU_AALO + off) = lb;
        }
        __syncthreads();

        const uint32_t aoff = (uint32_t)(stripe * 16 + (lane & 15)) * 208u
                              + (uint32_t)((lane >> 4) << 4);
        float D[6][4];
#pragma unroll
        for (int i = 0; i < 6; i++)
#pragma unroll
            for (int j = 0; j < 4; j++) D[i][j] = 0.0f;

        // ---- stage 1, pass h ----
        {
            uint32_t Ah[6][4], Al[6][4];
#pragma unroll
            for (int kt = 0; kt < 6; kt++) {
                ldsm_x4(Ah[kt], sbx + NU_AHHI + aoff + kt * 32);
                ldsm_x4(Al[kt], sbx + NU_AHLO + aoff + kt * 32);
            }
#pragma unroll
            for (int npl = 0; npl < 3; npl++) {
                const int np = nh * 3 + npl;
#pragma unroll
                for (int kt = 0; kt < 6; kt++) {
                    uint32_t Bh[4], Bl[4];
                    const uint32_t bko = (uint32_t)(kt * 16 + (lane & 15)) * 208u
                                         + (uint32_t)(np * 32) + ((lane >> 4) << 4);
                    ldsm_x4t(Bh, sbx + NU_B1HI + bko);
                    ldsm_x4t(Bl, sbx + NU_B1LO + bko);
                    mma16816(D[2 * npl], Ah[kt], Bh);
                    mma16816(D[2 * npl], Ah[kt], Bl);
                    mma16816(D[2 * npl], Al[kt], Bh);
                    mma16816(D[2 * npl + 1], Ah[kt], Bh + 2);
                    mma16816(D[2 * npl + 1], Ah[kt], Bl + 2);
                    mma16816(D[2 * npl + 1], Al[kt], Bh + 2);
                }
            }
        }
        // ---- stage 1, pass agg (B1 rows 96..191) ----
        {
            uint32_t Ah[6][4], Al[6][4];
#pragma unroll
            for (int kt = 0; kt < 6; kt++) {
                ldsm_x4(Ah[kt], sbx + NU_AAHI + aoff + kt * 32);
                ldsm_x4(Al[kt], sbx + NU_AALO + aoff + kt * 32);
            }
#pragma unroll
            for (int npl = 0; npl < 3; npl++) {
                const int np = nh * 3 + npl;
#pragma unroll
                for (int kt = 0; kt < 6; kt++) {
                    uint32_t Bh[4], Bl[4];
                    const uint32_t bko =
                        (uint32_t)(96 + kt * 16 + (lane & 15)) * 208u
                        + (uint32_t)(np * 32) + ((lane >> 4) << 4);
                    ldsm_x4t(Bh, sbx + NU_B1HI + bko);
                    ldsm_x4t(Bl, sbx + NU_B1LO + bko);
                    mma16816(D[2 * npl], Ah[kt], Bh);
                    mma16816(D[2 * npl], Ah[kt], Bl);
                    mma16816(D[2 * npl], Al[kt], Bh);
                    mma16816(D[2 * npl + 1], Ah[kt], Bh + 2);
                    mma16816(D[2 * npl + 1], Ah[kt], Bl + 2);
                    mma16816(D[2 * npl + 1], Al[kt], Bh + 2);
                }
            }
        }

        // ---- U = silu(D + b1) -> bf16 hi/lo into U smem ----
        {
            const int g = lane >> 2, q2 = 2 * (lane & 3);
            const int r0 = stripe * 16 + g;
#pragma unroll
            for (int i = 0; i < 6; i++) {
                const int col = (nh * 6 + i) * 8 + q2;
                const float u0 = silu_f(D[i][0] + b1s[col]);
                const float u1 = silu_f(D[i][1] + b1s[col + 1]);
                const float u2 = silu_f(D[i][2] + b1s[col]);
                const float u3 = silu_f(D[i][3] + b1s[col + 1]);
                __nv_bfloat16 h0, l0, h1, l1;
                split_bf16(u0, h0, l0);
                split_bf16(u1, h1, l1);
                *reinterpret_cast<__nv_bfloat162*>(smc + NU_UHI + r0 * 208 + 2 * col) =
                    __nv_bfloat162(h0, h1);
                *reinterpret_cast<__nv_bfloat162*>(smc + NU_ULO + r0 * 208 + 2 * col) =
                    __nv_bfloat162(l0, l1);
                split_bf16(u2, h0, l0);
                split_bf16(u3, h1, l1);
                *reinterpret_cast<__nv_bfloat162*>(smc + NU_UHI + (r0 + 8) * 208 + 2 * col) =
                    __nv_bfloat162(h0, h1);
                *reinterpret_cast<__nv_bfloat162*>(smc + NU_ULO + (r0 + 8) * 208 + 2 * col) =
                    __nv_bfloat162(l0, l1);
            }
        }
        __syncthreads();

        // ---- stage 2: O = U @ nW2 ----
        float O[6][4];
#pragma unroll
        for (int i = 0; i < 6; i++)
#pragma unroll
            for (int j = 0; j < 4; j++) O[i][j] = 0.0f;
        {
            uint32_t Uh[6][4], Ul[6][4];
#pragma unroll
            for (int kt = 0; kt < 6; kt++) {
                ldsm_x4(Uh[kt], sbx + NU_UHI + aoff + kt * 32);
                ldsm_x4(Ul[kt], sbx + NU_ULO + aoff + kt * 32);
            }
#pragma unroll
            for (int npl = 0; npl < 3; npl++) {
                const int np = nh * 3 + npl;
#pragma unroll
                for (int kt = 0; kt < 6; kt++) {
                    uint32_t Bh[4], Bl[4];
                    const uint32_t bko = (uint32_t)(kt * 16 + (lane & 15)) * 208u
                                         + (uint32_t)(np * 32) + ((lane >> 4) << 4);
                    ldsm_x4t(Bh, sbx + NU_B2HI + bko);
                    ldsm_x4t(Bl, sbx + NU_B2LO + bko);
                    mma16816(O[2 * npl], Uh[kt], Bh);
                    mma16816(O[2 * npl], Uh[kt], Bl);
                    mma16816(O[2 * npl], Ul[kt], Bh);
                    mma16816(O[2 * npl + 1], Uh[kt], Bh + 2);
                    mma16816(O[2 * npl + 1], Uh[kt], Bl + 2);
                    mma16816(O[2 * npl + 1], Ul[kt], Bh + 2);
                }
            }
        }

        // ---- epilogue: h += O + b2 ----
        {
            const int g = lane >> 2, q2 = 2 * (lane & 3);
            const int rA = base + stripe * 16 + g;
            const int rB = rA + 8;
#pragma unroll
            for (int i = 0; i < 6; i++) {
                const int col = (nh * 6 + i) * 8 + q2;
                if (rA < NN) {
                    float2 old = *(float2*)&g_h[rA * 96 + col];
                    *(float2*)&g_h[rA * 96 + col] =
                        make_float2(old.x + O[i][0] + b2s[col],
                                    old.y + O[i][1] + b2s[col + 1]);
                }
                if (rB < NN) {
                    float2 old = *(float2*)&g_h[rB * 96 + col];
                    *(float2*)&g_h[rB * 96 + col] =
                        make_float2(old.x + O[i][2] + b2s[col],
                                    old.y + O[i][3] + b2s[col + 1]);
                }
            }
        }
        __syncthreads();
    }
}

// ---------------------------------------------------------------------------
__global__ void __launch_bounds__(96) k_pool_acc(const int* __restrict__ batch) {
    const int j = threadIdx.x;
    for (int i = blockIdx.x; i < NN; i += gridDim.x) {
        const int b = batch[i];
        atomicAdd(&g_pool[b * HD + j], g_h[i * HD + j]);
        if (j == 0) atomicAdd(&g_cnt[b], 1.0f);
    }
}

__global__ void k_final(const float* __restrict__ Wl, const float* __restrict__ bl,
                        float* __restrict__ out) {
    const int b = threadIdx.x;
    if (b >= BB) return;
    float s = 0.0f;
#pragma unroll 8
    for (int jj = 0; jj < HD; jj++) s = fmaf(g_pool[b * HD + jj], Wl[jj], s);
    out[b] = s / fmaxf(g_cnt[b], 1.0f) + bl[0];
}

// ---------------------------------------------------------------------------
extern "C" void kernel_launch(void* const* d_in, const int* in_sizes, int n_in,
                              void* d_out, int out_size) {
    const float* x = (const float*)d_in[0];
    const float* pos = (const float*)d_in[1];
    const int* ei = (const int*)d_in[2];
    const float* edge_attr = (const float*)d_in[3];
    const int* batch = (const int*)d_in[4];
    const float* We = (const float*)d_in[5];
    const float* be = (const float*)d_in[6];
    const float* eW1 = (const float*)d_in[7];
    const float* eb1 = (const float*)d_in[8];
    const float* eW2 = (const float*)d_in[9];
    const float* eb2 = (const float*)d_in[10];
    const float* nW1 = (const float*)d_in[11];
    const float* nb1 = (const float*)d_in[12];
    const float* nW2 = (const float*)d_in[13];
    const float* nb2 = (const float*)d_in[14];
    const float* Wl = (const float*)d_in[15];
    const float* bl = (const float*)d_in[16];
    float* out = (float*)d_out;

    cudaFuncSetAttribute(k_node_pre, cudaFuncAttributeMaxDynamicSharedMemorySize,
                         NP_SMEM);
    cudaFuncSetAttribute(k_edge, cudaFuncAttributeMaxDynamicSharedMemorySize,
                         SMEM_EDGE);
    cudaFuncSetAttribute(k_node_update,
                         cudaFuncAttributeMaxDynamicSharedMemorySize, NU_SMEM);

    k_encoder<<<888, 96>>>(x, We, be);
    k_d2<<<3125, 256>>>(pos, ei);

    for (int l = 0; l < LL; ++l) {
        const float* eW1l = eW1 + l * 209 * HD;
        const float* eb1l = eb1 + l * HD;
        const float* eW2l = eW2 + l * HD * HD;
        const float* eb2l = eb2 + l * HD;
        const float* nW1l = nW1 + l * 2 * HD * HD;
        const float* nb1l = nb1 + l * HD;
        const float* nW2l = nW2 + l * HD * HD;
        const float* nb2l = nb2 + l * HD;

        k_node_pre<<<148, 512, NP_SMEM>>>(eW1l, eb1l);   // also zeroes g_agg
        k_edge<<<296, 256, SMEM_EDGE>>>(ei, edge_attr, eW1l, eW2l, eb2l);
        k_node_update<<<148, 256, NU_SMEM>>>(nW1l, nb1l, nW2l, nb2l);
    }

    k_zero_pool<<<20, 256>>>();
    k_pool_acc<<<1024, 96>>>(batch);
    k_final<<<1, 64>>>(Wl, bl, out);
}

// round 13
// speedup vs baseline: 4.0893x; 1.4556x over previous
#include <cuda_runtime.h>
#include <cuda_bf16.h>
#include <math.h>
#include <stdint.h>

#define NN 50000
#define EE 800000
#define HD 96
#define FIN 32
#define EDIM 16
#define LL 3
#define BB 50

// Scratch (device globals: no allocation allowed)
__device__ float g_h[NN * HD];
__device__ float g_Pb[NN * HD];
__device__ float g_Q[NN * HD];
__device__ float g_agg[NN * HD];
__device__ float g_d2[EE];
__device__ float g_pool[BB * HD];
__device__ float g_cnt[BB];

__device__ __forceinline__ float silu_f(float x) {
    return x / (1.0f + __expf(-x));
}

__device__ __forceinline__ void red_add2(float* p, float x, float y) {
    asm volatile("red.global.add.v2.f32 [%0], {%1,%2};"
                 :: "l"(p), "f"(x), "f"(y) : "memory");
}

// ---------------------------------------------------------------------------
// legacy tensor core helpers (sm_80+ : compile OK for plain sm_103 target)
// ---------------------------------------------------------------------------
__device__ __forceinline__ void ldsm_x4(uint32_t* r, uint32_t addr) {
    asm volatile("ldmatrix.sync.aligned.m8n8.x4.shared.b16 {%0,%1,%2,%3}, [%4];"
                 : "=r"(r[0]), "=r"(r[1]), "=r"(r[2]), "=r"(r[3]) : "r"(addr));
}
__device__ __forceinline__ void ldsm_x4t(uint32_t* r, uint32_t addr) {
    asm volatile("ldmatrix.sync.aligned.m8n8.x4.trans.shared.b16 {%0,%1,%2,%3}, [%4];"
                 : "=r"(r[0]), "=r"(r[1]), "=r"(r[2]), "=r"(r[3]) : "r"(addr));
}
__device__ __forceinline__ void mma16816(float* d, const uint32_t* a,
                                         const uint32_t* b) {
    asm volatile(
        "mma.sync.aligned.m16n8k16.row.col.f32.bf16.bf16.f32 "
        "{%0,%1,%2,%3}, {%4,%5,%6,%7}, {%8,%9}, {%0,%1,%2,%3};"
        : "+f"(d[0]), "+f"(d[1]), "+f"(d[2]), "+f"(d[3])
        : "r"(a[0]), "r"(a[1]), "r"(a[2]), "r"(a[3]), "r"(b[0]), "r"(b[1]));
}

__device__ __forceinline__ void split_bf16(float v, __nv_bfloat16& hb,
                                           __nv_bfloat16& lb) {
    hb = __float2bfloat16(v);
    lb = __float2bfloat16(v - __bfloat162float(hb));
}

// ---------------------------------------------------------------------------
// encoder: h = x @ We + be
// ---------------------------------------------------------------------------
__global__ void __launch_bounds__(96) k_encoder(const float* __restrict__ x,
                                                const float* __restrict__ We,
                                                const float* __restrict__ be) {
    __shared__ float sW[FIN * HD];
    __shared__ float sb[HD];
    __shared__ float xrow[FIN];
    const int j = threadIdx.x;
    for (int i = j; i < FIN * HD; i += 96) sW[i] = We[i];
    sb[j] = be[j];
    __syncthreads();
    for (int i = blockIdx.x; i < NN; i += gridDim.x) {
        if (j < FIN) xrow[j] = x[i * FIN + j];
        __syncthreads();
        float t = sb[j];
#pragma unroll
        for (int k = 0; k < FIN; k++) t = fmaf(xrow[k], sW[k * HD + j], t);
        g_h[i * HD + j] = t;
        __syncthreads();
    }
}

__global__ void k_d2(const float* __restrict__ pos, const int* __restrict__ ei) {
    for (int e = blockIdx.x * blockDim.x + threadIdx.x; e < EE;
         e += gridDim.x * blockDim.x) {
        const int s = ei[e], d = ei[EE + e];
        const float dx = pos[s * 3 + 0] - pos[d * 3 + 0];
        const float dy = pos[s * 3 + 1] - pos[d * 3 + 1];
        const float dz = pos[s * 3 + 2] - pos[d * 3 + 2];
        g_d2[e] = dx * dx + dy * dy + dz * dz;
    }
}

__global__ void k_zero_pool() {
    const int i = blockIdx.x * blockDim.x + threadIdx.x;
    if (i < BB * HD) g_pool[i] = 0.0f;
    if (i < BB) g_cnt[i] = 0.0f;
}

// ---------------------------------------------------------------------------
// node_pre (mma): [Pb|Q] = h @ [W1a|W1b] (+b1 on Pb). Also zeroes g_agg.
// ---------------------------------------------------------------------------
#define NP_BHI 0
#define NP_BLO 38400
#define NP_AHI 76800
#define NP_ALO 103424
#define NP_B1  130048
#define NP_SMEM 130432
#define NT_NP 391

__global__ void __launch_bounds__(512) k_node_pre(const float* __restrict__ eW1l,
                                                  const float* __restrict__ eb1l) {
    extern __shared__ char smc[];
    const uint32_t sbx = (uint32_t)__cvta_generic_to_shared(smc);
    const int t = threadIdx.x;
    const int lane = t & 31;
    const int w = t >> 5;
    const int stripe = w & 7;
    const int half = w >> 3;

    for (int idx = t; idx < 96 * 192; idx += 512) {
        const int k = idx / 192;
        const int n2 = idx - k * 192;
        const int srow = k + ((n2 >= 96) ? 96 : 0);
        const int scol = (n2 >= 96) ? (n2 - 96) : n2;
        __nv_bfloat16 hb, lb;
        split_bf16(eW1l[srow * 96 + scol], hb, lb);
        const int off = k * 400 + 2 * n2;
        *reinterpret_cast<__nv_bfloat16*>(smc + NP_BHI + off) = hb;
        *reinterpret_cast<__nv_bfloat16*>(smc + NP_BLO + off) = lb;
    }
    if (t < 96) ((float*)(smc + NP_B1))[t] = eb1l[t];
    __syncthreads();
    const float* b1s = (const float*)(smc + NP_B1);

    for (int tile = blockIdx.x; tile < NT_NP; tile += gridDim.x) {
        const int base = tile * 128;
        for (int idx = t; idx < 128 * 96; idx += 512) {
            const int r = idx / 96;
            const int c = idx - r * 96;
            const int gi = base + r;
            const float v = (gi < NN) ? g_h[gi * 96 + c] : 0.0f;
            __nv_bfloat16 hb, lb;
            split_bf16(v, hb, lb);
            const int off = r * 208 + 2 * c;
            *reinterpret_cast<__nv_bfloat16*>(smc + NP_AHI + off) = hb;
            *reinterpret_cast<__nv_bfloat16*>(smc + NP_ALO + off) = lb;
        }
        {
            const float4 z4 = make_float4(0.f, 0.f, 0.f, 0.f);
            for (int idx = t; idx < 128 * 24; idx += 512) {
                const int r = idx / 24;
                const int gi = base + r;
                if (gi < NN)
                    reinterpret_cast<float4*>(g_agg)[gi * 24 + (idx - r * 24)] = z4;
            }
        }
        __syncthreads();

        uint32_t Ah[6][4], Al[6][4];
        {
            const uint32_t aoff = (uint32_t)(stripe * 16 + (lane & 15)) * 208u
                                  + (uint32_t)((lane >> 4) << 4);
#pragma unroll
            for (int kt = 0; kt < 6; kt++) {
                ldsm_x4(Ah[kt], sbx + NP_AHI + aoff + kt * 32);
                ldsm_x4(Al[kt], sbx + NP_ALO + aoff + kt * 32);
            }
        }

#pragma unroll
        for (int npl = 0; npl < 6; npl++) {
            const int np = half * 6 + npl;
            float D0[4] = {0.f, 0.f, 0.f, 0.f};
            float D1[4] = {0.f, 0.f, 0.f, 0.f};
#pragma unroll
            for (int kt = 0; kt < 6; kt++) {
                uint32_t Bh[4], Bl[4];
                const uint32_t bko = (uint32_t)(kt * 16 + (lane & 15)) * 400u
                                     + (uint32_t)(np * 32) + ((lane >> 4) << 4);
                ldsm_x4t(Bh, sbx + NP_BHI + bko);
                ldsm_x4t(Bl, sbx + NP_BLO + bko);
                mma16816(D0, Ah[kt], Bh);
                mma16816(D0, Ah[kt], Bl);
                mma16816(D0, Al[kt], Bh);
                mma16816(D1, Ah[kt], Bh + 2);
                mma16816(D1, Ah[kt], Bl + 2);
                mma16816(D1, Al[kt], Bh + 2);
            }
            const int rA = base + stripe * 16 + (lane >> 2);
            const int rB = rA + 8;
            const int q2 = 2 * (lane & 3);
            if (np < 6) {
                const int c0 = (2 * np) * 8 + q2;
                const int c1 = c0 + 8;
                if (rA < NN) {
                    *(float2*)&g_Pb[rA * 96 + c0] =
                        make_float2(D0[0] + b1s[c0], D0[1] + b1s[c0 + 1]);
                    *(float2*)&g_Pb[rA * 96 + c1] =
                        make_float2(D1[0] + b1s[c1], D1[1] + b1s[c1 + 1]);
                }
                if (rB < NN) {
                    *(float2*)&g_Pb[rB * 96 + c0] =
                        make_float2(D0[2] + b1s[c0], D0[3] + b1s[c0 + 1]);
                    *(float2*)&g_Pb[rB * 96 + c1] =
                        make_float2(D1[2] + b1s[c1], D1[3] + b1s[c1 + 1]);
                }
            } else {
                const int c0 = (2 * np) * 8 + q2 - 96;
                const int c1 = c0 + 8;
                if (rA < NN) {
                    *(float2*)&g_Q[rA * 96 + c0] = make_float2(D0[0], D0[1]);
                    *(float2*)&g_Q[rA * 96 + c1] = make_float2(D1[0], D1[1]);
                }
                if (rB < NN) {
                    *(float2*)&g_Q[rB * 96 + c0] = make_float2(D0[2], D0[3]);
                    *(float2*)&g_Q[rB * 96 + c1] = make_float2(D1[2], D1[3]);
                }
            }
        }
        __syncthreads();
    }
}

// ---------------------------------------------------------------------------
// fused edge kernel — warp-independent 16-edge stripes, no block barriers.
// Per stripe (per warp):
//   stage src/dst/d2/ea (ea split to bf16 hi/lo)
//   D = ea @ W1c (mma, 3-term) ; D += Pb[src]+Q[dst]+wd*d2 (float2 gathers)
//   u = silu(D) -> bf16 hi/lo into warp-private smem rows
//   O = u @ W2 (mma, 3-term) ; epilogue silu(O+b2) -> red.add.v2 g_agg[dst]
// ---------------------------------------------------------------------------
#define EK_W2HI 0
#define EK_W2LO 19968
#define EK_W1CHI 39936
#define EK_W1CLO 43264
#define EK_WD 46592
#define EK_B2 46976
#define EK_UHI 47360
#define EK_ULO 73984
#define EK_EAHI 100608
#define EK_EALO 106752
#define EK_SRC 112896
#define EK_DST 113408
#define EK_D2S 113920
#define EK_SMEM 114432
#define NSTRIPE (EE / 16)

__global__ void __launch_bounds__(256, 2) k_edge(const int* __restrict__ ei,
                                                 const float* __restrict__ edge_attr,
                                                 const float* __restrict__ eW1l,
                                                 const float* __restrict__ eW2l,
                                                 const float* __restrict__ eb2l) {
    extern __shared__ char smc[];
    const uint32_t sbx = (uint32_t)__cvta_generic_to_shared(smc);
    const int t = threadIdx.x;
    const int lane = t & 31;
    const int w = t >> 5;

    // ---- one-time setup (block-wide) ----
    for (int idx = t; idx < HD * HD; idx += 256) {
        const int k = idx / HD, n = idx % HD;
        __nv_bfloat16 hb, lb;
        split_bf16(eW2l[idx], hb, lb);
        *reinterpret_cast<__nv_bfloat16*>(smc + EK_W2HI + k * 208 + 2 * n) = hb;
        *reinterpret_cast<__nv_bfloat16*>(smc + EK_W2LO + k * 208 + 2 * n) = lb;
    }
    for (int idx = t; idx < EDIM * HD; idx += 256) {
        const int k = idx / HD, n = idx % HD;
        __nv_bfloat16 hb, lb;
        split_bf16(eW1l[(193 + k) * HD + n], hb, lb);
        *reinterpret_cast<__nv_bfloat16*>(smc + EK_W1CHI + k * 208 + 2 * n) = hb;
        *reinterpret_cast<__nv_bfloat16*>(smc + EK_W1CLO + k * 208 + 2 * n) = lb;
    }
    if (t < HD) {
        ((float*)(smc + EK_WD))[t] = eW1l[192 * HD + t];
        ((float*)(smc + EK_B2))[t] = eb2l[t];
    }
    __syncthreads();

    const float* wds = (const float*)(smc + EK_WD);
    const float* b2s = (const float*)(smc + EK_B2);
    int* s_srcw = (int*)(smc + EK_SRC + w * 64);
    int* s_dstw = (int*)(smc + EK_DST + w * 64);
    float* s_d2w = (float*)(smc + EK_D2S + w * 64);
    const uint32_t u_hi = sbx + EK_UHI + w * 3328;
    const uint32_t u_lo = sbx + EK_ULO + w * 3328;
    const uint32_t ea_hi = sbx + EK_EAHI + w * 768;
    const uint32_t ea_lo = sbx + EK_EALO + w * 768;

    const int r0 = lane >> 2;
    const int r1 = r0 + 8;
    const int q2 = 2 * (lane & 3);
    const int wgid = blockIdx.x * 8 + w;
    const int wstride = gridDim.x * 8;

    for (int sp = wgid; sp < NSTRIPE; sp += wstride) {
        const int e_base = sp * 16;

        // ---- stage (warp-private) ----
        if (lane < 16) {
            s_srcw[lane] = ei[e_base + lane];
            s_dstw[lane] = ei[EE + e_base + lane];
            s_d2w[lane] = g_d2[e_base + lane];
        }
#pragma unroll
        for (int i = 0; i < 4; i++) {
            const int p = lane + 32 * i;       // 128 float2-pairs = 16 edges x 8
            const int el = p >> 3, kp = p & 7;
            const float2 v = *reinterpret_cast<const float2*>(
                edge_attr + (size_t)(e_base + el) * EDIM + 2 * kp);
            __nv_bfloat16 h0, l0, h1, l1;
            split_bf16(v.x, h0, l0);
            split_bf16(v.y, h1, l1);
            *reinterpret_cast<__nv_bfloat162*>(smc + EK_EAHI + w * 768 + el * 48 + kp * 4) =
                __nv_bfloat162(h0, h1);
            *reinterpret_cast<__nv_bfloat162*>(smc + EK_EALO + w * 768 + el * 48 + kp * 4) =
                __nv_bfloat162(l0, l1);
        }
        __syncwarp();

        // ---- mma1: D = ea @ W1c (K=16) ----
        float D[12][4];
#pragma unroll
        for (int nt = 0; nt < 12; nt++)
#pragma unroll
            for (int i = 0; i < 4; i++) D[nt][i] = 0.0f;
        {
            uint32_t Eh[4], El[4];
            const uint32_t eoff = (uint32_t)(lane & 15) * 48u + ((lane >> 4) << 4);
            ldsm_x4(Eh, ea_hi + eoff);
            ldsm_x4(El, ea_lo + eoff);
#pragma unroll
            for (int np = 0; np < 6; np++) {
                uint32_t Bh[4], Bl[4];
                const uint32_t bko = (uint32_t)(lane & 15) * 208u
                                     + (uint32_t)(np * 32) + ((lane >> 4) << 4);
                ldsm_x4t(Bh, sbx + EK_W1CHI + bko);
                ldsm_x4t(Bl, sbx + EK_W1CLO + bko);
                mma16816(D[2 * np], Eh, Bh);
                mma16816(D[2 * np], Eh, Bl);
                mma16816(D[2 * np], El, Bh);
                mma16816(D[2 * np + 1], Eh, Bh + 2);
                mma16816(D[2 * np + 1], Eh, Bl + 2);
                mma16816(D[2 * np + 1], El, Bh + 2);
            }
        }

        // ---- gather-add: D += Pb[src] + Q[dst] + wd*d2 (fragment layout) ----
        const int s0 = s_srcw[r0], d0 = s_dstw[r0];
        const int s1 = s_srcw[r1], d1 = s_dstw[r1];
        const float d2r0 = s_d2w[r0], d2r1 = s_d2w[r1];
        const float* pb0 = g_Pb + (size_t)s0 * 96;
        const float* qq0 = g_Q + (size_t)d0 * 96;
        const float* pb1 = g_Pb + (size_t)s1 * 96;
        const float* qq1 = g_Q + (size_t)d1 * 96;
#pragma unroll
        for (int nt = 0; nt < 12; nt++) {
            const int c = nt * 8 + q2;
            const float2 wv = *reinterpret_cast<const float2*>(wds + c);
            const float2 a0 = *reinterpret_cast<const float2*>(pb0 + c);
            const float2 b0 = *reinterpret_cast<const float2*>(qq0 + c);
            const float2 a1 = *reinterpret_cast<const float2*>(pb1 + c);
            const float2 b1 = *reinterpret_cast<const float2*>(qq1 + c);
            D[nt][0] += a0.x + b0.x + d2r0 * wv.x;
            D[nt][1] += a0.y + b0.y + d2r0 * wv.y;
            D[nt][2] += a1.x + b1.x + d2r1 * wv.x;
            D[nt][3] += a1.y + b1.y + d2r1 * wv.y;
        }

        // ---- u = silu(D) -> bf16 hi/lo, warp-private rows ----
#pragma unroll
        for (int nt = 0; nt < 12; nt++) {
            const int c = nt * 8 + q2;
            const float u0 = silu_f(D[nt][0]), u1 = silu_f(D[nt][1]);
            const float u2 = silu_f(D[nt][2]), u3 = silu_f(D[nt][3]);
            __nv_bfloat16 h0, l0, h1, l1;
            split_bf16(u0, h0, l0);
            split_bf16(u1, h1, l1);
            *reinterpret_cast<__nv_bfloat162*>(smc + EK_UHI + w * 3328 + r0 * 208 + 2 * c) =
                __nv_bfloat162(h0, h1);
            *reinterpret_cast<__nv_bfloat162*>(smc + EK_ULO + w * 3328 + r0 * 208 + 2 * c) =
                __nv_bfloat162(l0, l1);
            split_bf16(u2, h0, l0);
            split_bf16(u3, h1, l1);
            *reinterpret_cast<__nv_bfloat162*>(smc + EK_UHI + w * 3328 + r1 * 208 + 2 * c) =
                __nv_bfloat162(h0, h1);
            *reinterpret_cast<__nv_bfloat162*>(smc + EK_ULO + w * 3328 + r1 * 208 + 2 * c) =
                __nv_bfloat162(l0, l1);
        }
        __syncwarp();

        // ---- mma2: O = u @ W2 ----
        uint32_t Ah[6][4], Al[6][4];
        {
            const uint32_t aoff = (uint32_t)(lane & 15) * 208u + ((lane >> 4) << 4);
#pragma unroll
            for (int kt = 0; kt < 6; kt++) {
                ldsm_x4(Ah[kt], u_hi + aoff + kt * 32);
                ldsm_x4(Al[kt], u_lo + aoff + kt * 32);
            }
        }
        float O[12][4];
#pragma unroll
        for (int nt = 0; nt < 12; nt++)
#pragma unroll
            for (int i = 0; i < 4; i++) O[nt][i] = 0.0f;
#pragma unroll
        for (int kt = 0; kt < 6; kt++) {
            const uint32_t bko = (uint32_t)(kt * 16 + (lane & 15)) * 208u
                                 + ((lane >> 4) << 4);
#pragma unroll
            for (int np = 0; np < 6; np++) {
                uint32_t Bh[4], Bl[4];
                ldsm_x4t(Bh, sbx + EK_W2HI + bko + np * 32);
                ldsm_x4t(Bl, sbx + EK_W2LO + bko + np * 32);
                mma16816(O[2 * np], Ah[kt], Bh);
                mma16816(O[2 * np], Ah[kt], Bl);
                mma16816(O[2 * np], Al[kt], Bh);
                mma16816(O[2 * np + 1], Ah[kt], Bh + 2);
                mma16816(O[2 * np + 1], Ah[kt], Bl + 2);
                mma16816(O[2 * np + 1], Al[kt], Bh + 2);
            }
        }

        // ---- epilogue: silu(O + b2) -> red.add.v2 into g_agg[dst] ----
        float* agg0 = g_agg + (size_t)d0 * 96;
        float* agg1 = g_agg + (size_t)d1 * 96;
#pragma unroll
        for (int nt = 0; nt < 12; nt++) {
            const int c = nt * 8 + q2;
            const float2 bv = *reinterpret_cast<const float2*>(b2s + c);
            red_add2(agg0 + c, silu_f(O[nt][0] + bv.x), silu_f(O[nt][1] + bv.y));
            red_add2(agg1 + c, silu_f(O[nt][2] + bv.x), silu_f(O[nt][3] + bv.y));
        }
    }
}

// ---------------------------------------------------------------------------
// node update (mma): h += silu([h|agg] @ nW1 + nb1) @ nW2 + nb2
// ---------------------------------------------------------------------------
#define NU_B1HI 0
#define NU_B1LO 39936
#define NU_B2HI 79872
#define NU_B2LO 99840
#define NU_AHHI 119808
#define NU_AHLO 133120
#define NU_AAHI 146432
#define NU_AALO 159744
#define NU_UHI  173056
#define NU_ULO  186368
#define NU_NB1  199680
#define NU_NB2  200064
#define NU_SMEM 200448
#define NT_NU 782

__global__ void __launch_bounds__(256) k_node_update(const float* __restrict__ nW1l,
                                                     const float* __restrict__ nb1l,
                                                     const float* __restrict__ nW2l,
                                                     const float* __restrict__ nb2l) {
    extern __shared__ char smc[];
    const uint32_t sbx = (uint32_t)__cvta_generic_to_shared(smc);
    const int t = threadIdx.x;
    const int lane = t & 31;
    const int w = t >> 5;
    const int stripe = w & 3;
    const int nh = w >> 2;

    for (int idx = t; idx < 192 * 96; idx += 256) {
        const int k = idx / 96, n = idx - (idx / 96) * 96;
        __nv_bfloat16 hb, lb;
        split_bf16(nW1l[idx], hb, lb);
        *reinterpret_cast<__nv_bfloat16*>(smc + NU_B1HI + k * 208 + 2 * n) = hb;
        *reinterpret_cast<__nv_bfloat16*>(smc + NU_B1LO + k * 208 + 2 * n) = lb;
    }
    for (int idx = t; idx < 96 * 96; idx += 256) {
        const int k = idx / 96, n = idx - (idx / 96) * 96;
        __nv_bfloat16 hb, lb;
        split_bf16(nW2l[idx], hb, lb);
        *reinterpret_cast<__nv_bfloat16*>(smc + NU_B2HI + k * 208 + 2 * n) = hb;
        *reinterpret_cast<__nv_bfloat16*>(smc + NU_B2LO + k * 208 + 2 * n) = lb;
    }
    if (t < 96) {
        ((float*)(smc + NU_NB1))[t] = nb1l[t];
        ((float*)(smc + NU_NB2))[t] = nb2l[t];
    }
    __syncthreads();
    const float* b1s = (const float*)(smc + NU_NB1);
    const float* b2s = (const float*)(smc + NU_NB2);

    for (int tile = blockIdx.x; tile < NT_NU; tile += gridDim.x) {
        const int base = tile * 64;
        for (int idx = t; idx < 64 * 96; idx += 256) {
            const int r = idx / 96;
            const int c = idx - r * 96;
            const int gi = base + r;
            const int off = r * 208 + 2 * c;
            float vh = 0.f, va = 0.f;
            if (gi < NN) {
                vh = g_h[gi * 96 + c];
                va = g_agg[gi * 96 + c];
            }
            __nv_bfloat16 hb, lb;
            split_bf16(vh, hb, lb);
            *reinterpret_cast<__nv_bfloat16*>(smc + NU_AHHI + off) = hb;
            *reinterpret_cast<__nv_bfloat16*>(smc + NU_AHLO + off) = lb;
            split_bf16(va, hb, lb);
            *reinterpret_cast<__nv_bfloat16*>(smc + NU_AAHI + off) = hb;
            *reinterpret_cast<__nv_bfloat16*>(smc + NU_AALO + off) = lb;
        }
        __syncthreads();

        const uint32_t aoff = (uint32_t)(stripe * 16 + (lane & 15)) * 208u
                              + (uint32_t)((lane >> 4) << 4);
        float D[6][4];
#pragma unroll
        for (int i = 0; i < 6; i++)
#pragma unroll
            for (int j = 0; j < 4; j++) D[i][j] = 0.0f;

        {
            uint32_t Ah[6][4], Al[6][4];
#pragma unroll
            for (int kt = 0; kt < 6; kt++) {
                ldsm_x4(Ah[kt], sbx + NU_AHHI + aoff + kt * 32);
                ldsm_x4(Al[kt], sbx + NU_AHLO + aoff + kt * 32);
            }
#pragma unroll
            for (int npl = 0; npl < 3; npl++) {
                const int np = nh * 3 + npl;
#pragma unroll
                for (int kt = 0; kt < 6; kt++) {
                    uint32_t Bh[4], Bl[4];
                    const uint32_t bko = (uint32_t)(kt * 16 + (lane & 15)) * 208u
                                         + (uint32_t)(np * 32) + ((lane >> 4) << 4);
                    ldsm_x4t(Bh, sbx + NU_B1HI + bko);
                    ldsm_x4t(Bl, sbx + NU_B1LO + bko);
                    mma16816(D[2 * npl], Ah[kt], Bh);
                    mma16816(D[2 * npl], Ah[kt], Bl);
                    mma16816(D[2 * npl], Al[kt], Bh);
                    mma16816(D[2 * npl + 1], Ah[kt], Bh + 2);
                    mma16816(D[2 * npl + 1], Ah[kt], Bl + 2);
                    mma16816(D[2 * npl + 1], Al[kt], Bh + 2);
                }
            }
        }
        {
            uint32_t Ah[6][4], Al[6][4];
#pragma unroll
            for (int kt = 0; kt < 6; kt++) {
                ldsm_x4(Ah[kt], sbx + NU_AAHI + aoff + kt * 32);
                ldsm_x4(Al[kt], sbx + NU_AALO + aoff + kt * 32);
            }
#pragma unroll
            for (int npl = 0; npl < 3; npl++) {
                const int np = nh * 3 + npl;
#pragma unroll
                for (int kt = 0; kt < 6; kt++) {
                    uint32_t Bh[4], Bl[4];
                    const uint32_t bko =
                        (uint32_t)(96 + kt * 16 + (lane & 15)) * 208u
                        + (uint32_t)(np * 32) + ((lane >> 4) << 4);
                    ldsm_x4t(Bh, sbx + NU_B1HI + bko);
                    ldsm_x4t(Bl, sbx + NU_B1LO + bko);
                    mma16816(D[2 * npl], Ah[kt], Bh);
                    mma16816(D[2 * npl], Ah[kt], Bl);
                    mma16816(D[2 * npl], Al[kt], Bh);
                    mma16816(D[2 * npl + 1], Ah[kt], Bh + 2);
                    mma16816(D[2 * npl + 1], Ah[kt], Bl + 2);
                    mma16816(D[2 * npl + 1], Al[kt], Bh + 2);
                }
            }
        }

        {
            const int g = lane >> 2, q2 = 2 * (lane & 3);
            const int r0 = stripe * 16 + g;
#pragma unroll
            for (int i = 0; i < 6; i++) {
                const int col = (nh * 6 + i) * 8 + q2;
                const float u0 = silu_f(D[i][0] + b1s[col]);
                const float u1 = silu_f(D[i][1] + b1s[col + 1]);
                const float u2 = silu_f(D[i][2] + b1s[col]);
                const float u3 = silu_f(D[i][3] + b1s[col + 1]);
                __nv_bfloat16 h0, l0, h1, l1;
                split_bf16(u0, h0, l0);
                split_bf16(u1, h1, l1);
                *reinterpret_cast<__nv_bfloat162*>(smc + NU_UHI + r0 * 208 + 2 * col) =
                    __nv_bfloat162(h0, h1);
                *reinterpret_cast<__nv_bfloat162*>(smc + NU_ULO + r0 * 208 + 2 * col) =
                    __nv_bfloat162(l0, l1);
                split_bf16(u2, h0, l0);
                split_bf16(u3, h1, l1);
                *reinterpret_cast<__nv_bfloat162*>(smc + NU_UHI + (r0 + 8) * 208 + 2 * col) =
                    __nv_bfloat162(h0, h1);
                *reinterpret_cast<__nv_bfloat162*>(smc + NU_ULO + (r0 + 8) * 208 + 2 * col) =
                    __nv_bfloat162(l0, l1);
            }
        }
        __syncthreads();

        float O[6][4];
#pragma unroll
        for (int i = 0; i < 6; i++)
#pragma unroll
            for (int j = 0; j < 4; j++) O[i][j] = 0.0f;
        {
            uint32_t Uh[6][4], Ul[6][4];
#pragma unroll
            for (int kt = 0; kt < 6; kt++) {
                ldsm_x4(Uh[kt], sbx + NU_UHI + aoff + kt * 32);
                ldsm_x4(Ul[kt], sbx + NU_ULO + aoff + kt * 32);
            }
#pragma unroll
            for (int npl = 0; npl < 3; npl++) {
                const int np = nh * 3 + npl;
#pragma unroll
                for (int kt = 0; kt < 6; kt++) {
                    uint32_t Bh[4], Bl[4];
                    const uint32_t bko = (uint32_t)(kt * 16 + (lane & 15)) * 208u
                                         + (uint32_t)(np * 32) + ((lane >> 4) << 4);
                    ldsm_x4t(Bh, sbx + NU_B2HI + bko);
                    ldsm_x4t(Bl, sbx + NU_B2LO + bko);
                    mma16816(O[2 * npl], Uh[kt], Bh);
                    mma16816(O[2 * npl], Uh[kt], Bl);
                    mma16816(O[2 * npl], Ul[kt], Bh);
                    mma16816(O[2 * npl + 1], Uh[kt], Bh + 2);
                    mma16816(O[2 * npl + 1], Uh[kt], Bl + 2);
                    mma16816(O[2 * npl + 1], Ul[kt], Bh + 2);
                }
            }
        }

        {
            const int g = lane >> 2, q2 = 2 * (lane & 3);
            const int rA = base + stripe * 16 + g;
            const int rB = rA + 8;
#pragma unroll
            for (int i = 0; i < 6; i++) {
                const int col = (nh * 6 + i) * 8 + q2;
                if (rA < NN) {
                    float2 old = *(float2*)&g_h[rA * 96 + col];
                    *(float2*)&g_h[rA * 96 + col] =
                        make_float2(old.x + O[i][0] + b2s[col],
                                    old.y + O[i][1] + b2s[col + 1]);
                }
                if (rB < NN) {
                    float2 old = *(float2*)&g_h[rB * 96 + col];
                    *(float2*)&g_h[rB * 96 + col] =
                        make_float2(old.x + O[i][2] + b2s[col],
                                    old.y + O[i][3] + b2s[col + 1]);
                }
            }
        }
        __syncthreads();
    }
}

// ---------------------------------------------------------------------------
__global__ void __launch_bounds__(96) k_pool_acc(const int* __restrict__ batch) {
    const int j = threadIdx.x;
    for (int i = blockIdx.x; i < NN; i += gridDim.x) {
        const int b = batch[i];
        atomicAdd(&g_pool[b * HD + j], g_h[i * HD + j]);
        if (j == 0) atomicAdd(&g_cnt[b], 1.0f);
    }
}

__global__ void k_final(const float* __restrict__ Wl, const float* __restrict__ bl,
                        float* __restrict__ out) {
    const int b = threadIdx.x;
    if (b >= BB) return;
    float s = 0.0f;
#pragma unroll 8
    for (int jj = 0; jj < HD; jj++) s = fmaf(g_pool[b * HD + jj], Wl[jj], s);
    out[b] = s / fmaxf(g_cnt[b], 1.0f) + bl[0];
}

// ---------------------------------------------------------------------------
extern "C" void kernel_launch(void* const* d_in, const int* in_sizes, int n_in,
                              void* d_out, int out_size) {
    const float* x = (const float*)d_in[0];
    const float* pos = (const float*)d_in[1];
    const int* ei = (const int*)d_in[2];
    const float* edge_attr = (const float*)d_in[3];
    const int* batch = (const int*)d_in[4];
    const float* We = (const float*)d_in[5];
    const float* be = (const float*)d_in[6];
    const float* eW1 = (const float*)d_in[7];
    const float* eb1 = (const float*)d_in[8];
    const float* eW2 = (const float*)d_in[9];
    const float* eb2 = (const float*)d_in[10];
    const float* nW1 = (const float*)d_in[11];
    const float* nb1 = (const float*)d_in[12];
    const float* nW2 = (const float*)d_in[13];
    const float* nb2 = (const float*)d_in[14];
    const float* Wl = (const float*)d_in[15];
    const float* bl = (const float*)d_in[16];
    float* out = (float*)d_out;

    cudaFuncSetAttribute(k_node_pre, cudaFuncAttributeMaxDynamicSharedMemorySize,
                         NP_SMEM);
    cudaFuncSetAttribute(k_edge, cudaFuncAttributeMaxDynamicSharedMemorySize,
                         EK_SMEM);
    cudaFuncSetAttribute(k_node_update,
                         cudaFuncAttributeMaxDynamicSharedMemorySize, NU_SMEM);

    k_encoder<<<888, 96>>>(x, We, be);
    k_d2<<<3125, 256>>>(pos, ei);

    for (int l = 0; l < LL; ++l) {
        const float* eW1l = eW1 + l * 209 * HD;
        const float* eb1l = eb1 + l * HD;
        const float* eW2l = eW2 + l * HD * HD;
        const float* eb2l = eb2 + l * HD;
        const float* nW1l = nW1 + l * 2 * HD * HD;
        const float* nb1l = nb1 + l * HD;
        const float* nW2l = nW2 + l * HD * HD;
        const float* nb2l = nb2 + l * HD;

        k_node_pre<<<148, 512, NP_SMEM>>>(eW1l, eb1l);   // also zeroes g_agg
        k_edge<<<296, 256, EK_SMEM>>>(ei, edge_attr, eW1l, eW2l, eb2l);
        k_node_update<<<148, 256, NU_SMEM>>>(nW1l, nb1l, nW2l, nb2l);
    }

    k_zero_pool<<<20, 256>>>();
    k_pool_acc<<<1024, 96>>>(batch);
    k_final<<<1, 64>>>(Wl, bl, out);
}